// round 13
// baseline (speedup 1.0000x reference)
#include <cuda_runtime.h>
#include <cuda_fp16.h>
#include <math.h>
#include <stdint.h>

// Problem constants
#define S_TOK   8192
#define HDIM    1024
#define NHEAD   16
#define HD      64
#define MLPD    4096
#define NSEG    8
#define LSEG    1024

// Scratch buffers (half-precision activations; fp32 residual spine)
__device__ __half g_h   [S_TOK * HDIM];     // ln0 out
__device__ __half g_qkv [S_TOK * 3 * HDIM]; // rope applied in epilogue
__device__ __half g_attn[S_TOK * HDIM];     // fa out
__device__ float  g_x1  [S_TOK * HDIM];     // x + attn@wo^T (f32)
__device__ __half g_h2  [S_TOK * HDIM];     // ln1 out
__device__ __half g_mid [S_TOK * MLPD];     // gelu(fc0)
// pre-converted weights (half)
__device__ __half g_wqkv_t[3 * HDIM * HDIM];
__device__ __half g_wo_t  [HDIM * HDIM];
__device__ __half g_fc0_t [MLPD * HDIM];
__device__ __half g_fc1_t [HDIM * MLPD];

__device__ __forceinline__ uint32_t smem_u32(const void* p) {
    uint32_t a;
    asm("{ .reg .u64 t; cvta.to.shared.u64 t, %1; cvt.u32.u64 %0, t; }" : "=r"(a) : "l"(p));
    return a;
}
__device__ __forceinline__ uint32_t pack_h2(float a, float b) {
    __half2 h = __float22half2_rn(make_float2(a, b));
    return *reinterpret_cast<uint32_t*>(&h);
}
__device__ __forceinline__ void mma_f16(float* d, const uint32_t* a, const uint32_t* b) {
    asm volatile(
        "mma.sync.aligned.m16n8k16.row.col.f32.f16.f16.f32 "
        "{%0,%1,%2,%3}, {%4,%5,%6,%7}, {%8,%9}, {%0,%1,%2,%3};"
        : "+f"(d[0]), "+f"(d[1]), "+f"(d[2]), "+f"(d[3])
        : "r"(a[0]), "r"(a[1]), "r"(a[2]), "r"(a[3]), "r"(b[0]), "r"(b[1]));
}
__device__ __forceinline__ void ldm4(uint32_t* r, uint32_t addr) {
    asm volatile("ldmatrix.sync.aligned.m8n8.x4.shared.b16 {%0,%1,%2,%3}, [%4];"
                 : "=r"(r[0]), "=r"(r[1]), "=r"(r[2]), "=r"(r[3]) : "r"(addr));
}
__device__ __forceinline__ void ldm4t(uint32_t* r, uint32_t addr) {
    asm volatile("ldmatrix.sync.aligned.m8n8.x4.trans.shared.b16 {%0,%1,%2,%3}, [%4];"
                 : "=r"(r[0]), "=r"(r[1]), "=r"(r[2]), "=r"(r[3]) : "r"(addr));
}
__device__ __forceinline__ void cp16(uint32_t dst, const void* src) {
    asm volatile("cp.async.cg.shared.global [%0], [%1], 16;" :: "r"(dst), "l"(src) : "memory");
}

// ---------------------------------------------------------------------------
// fp16 mma.sync GEMM: C[M,N] = A[M,K] @ B[N,K]^T (+ epilogue)
// 128x128 tile, BK=64 halves, 256 threads (2x4 warps), 64x32 warp tile.
// 3-stage cp.async ring, one __syncthreads per chunk, 2 CTAs/SM.
// EPI: 1=+res, 2=+bias+GELU, 3=+bias+res, 4=rope(cols<2048)
// OUTH: 1 -> write half, 0 -> write f32
// ---------------------------------------------------------------------------
#define STRD 72                                  // halves per smem row (144 B)
#define AOFF_B (128 * STRD * 2)                  // 18432 B
#define STAGE_BYTES (2 * 128 * STRD * 2)         // 36864 B
#define GEMM_SMEM (3 * STAGE_BYTES)              // 110592 B

template <int EPI, int OUTH>
__global__ void __launch_bounds__(256, 2)
tc_gemm(const __half* __restrict__ A, const __half* __restrict__ B,
        void* __restrict__ Cv, const float* __restrict__ bias,
        const float* __restrict__ res,
        const float* __restrict__ cosb, const float* __restrict__ sinb,
        int M, int N, int K)
{
    extern __shared__ uint32_t sm4[];
    const uint32_t smb = smem_u32(sm4);

    const int tid  = threadIdx.x;
    const int wid  = tid >> 5;
    const int lane = tid & 31;
    const int warp_m = wid >> 2;   // 0..1
    const int warp_n = wid & 3;    // 0..3
    const int lr = lane >> 2;
    const int lc = lane & 3;

    const __half* Ab = A + (size_t)blockIdx.y * 128 * K;
    const __half* Bb = B + (size_t)blockIdx.x * 128 * K;

    float acc[16][4];
    #pragma unroll
    for (int i = 0; i < 16; i++)
        #pragma unroll
        for (int j = 0; j < 4; j++) acc[i][j] = 0.f;

    const int NC = K >> 6;

    const uint32_t aFragOff = ((warp_m * 64 + (lane & 15)) * STRD + (lane >> 4) * 8) * 2;
    const uint32_t bFragOff = AOFF_B +
        ((warp_n * 32 + (lane & 15)) * STRD + (lane >> 4) * 8) * 2;

    auto issue = [&](int c, int b) {
        const int k0 = c << 6;
        const uint32_t base = smb + (uint32_t)b * STAGE_BYTES;
        #pragma unroll
        for (int i = 0; i < 4; i++) {
            int f = i * 256 + tid;                 // 0..1023
            int row = f >> 3, c16 = (f & 7) * 8;   // c16 in halves
            cp16(base + (uint32_t)(row * STRD + c16) * 2,
                 Ab + (size_t)row * K + k0 + c16);
            cp16(base + AOFF_B + (uint32_t)(row * STRD + c16) * 2,
                 Bb + (size_t)row * K + k0 + c16);
        }
        asm volatile("cp.async.commit_group;" ::: "memory");
    };

    issue(0, 0);
    issue(1, 1);

    for (int c = 0; c < NC; c++) {
        if (c + 1 < NC) {
            asm volatile("cp.async.wait_group 1;" ::: "memory");
        } else {
            asm volatile("cp.async.wait_group 0;" ::: "memory");
        }
        __syncthreads();

        if (c + 2 < NC) issue(c + 2, (c + 2) % 3);

        const uint32_t sb = smb + (uint32_t)(c % 3) * STAGE_BYTES;
        const uint32_t aB = sb + aFragOff;
        const uint32_t bB = sb + bFragOff;
        #pragma unroll
        for (int ks = 0; ks < 4; ks++) {           // 4 k-steps of 16
            uint32_t afr[4][4], bfr[4][2];
            #pragma unroll
            for (int mt = 0; mt < 4; mt++)
                ldm4(afr[mt], aB + (uint32_t)(mt * 16 * STRD + ks * 16) * 2);
            #pragma unroll
            for (int g = 0; g < 2; g++) {
                uint32_t t[4];
                ldm4(t, bB + (uint32_t)(g * 16 * STRD + ks * 16) * 2);
                bfr[2 * g][0] = t[0]; bfr[2 * g][1] = t[2];
                bfr[2 * g + 1][0] = t[1]; bfr[2 * g + 1][1] = t[3];
            }
            #pragma unroll
            for (int mt = 0; mt < 4; mt++)
                #pragma unroll
                for (int nt = 0; nt < 4; nt++)
                    mma_f16(acc[mt * 4 + nt], afr[mt], bfr[nt]);
        }
    }

    // Epilogue
    #pragma unroll
    for (int mt = 0; mt < 4; mt++) {
        #pragma unroll
        for (int h = 0; h < 2; h++) {
            int row = blockIdx.y * 128 + warp_m * 64 + mt * 16 + lr + h * 8;
            #pragma unroll
            for (int nt = 0; nt < 4; nt++) {
                int col = blockIdx.x * 128 + warp_n * 32 + nt * 8 + lc * 2;
                float v0 = acc[mt * 4 + nt][h * 2 + 0];
                float v1 = acc[mt * 4 + nt][h * 2 + 1];
                if (EPI == 2 || EPI == 3) {
                    v0 += bias[col];
                    v1 += bias[col + 1];
                }
                if (EPI == 2) {
                    v0 = 0.5f * v0 * (1.f + erff(v0 * 0.70710678118f));
                    v1 = 0.5f * v1 * (1.f + erff(v1 * 0.70710678118f));
                }
                if (EPI == 1 || EPI == 3) {
                    v0 += res[(size_t)row * N + col];
                    v1 += res[(size_t)row * N + col + 1];
                }
                if (EPI == 4) {
                    if (col < 2048) {
                        int i = (col & 63) >> 1;
                        float cc = cosb[row * 32 + i];
                        float ss = sinb[row * 32 + i];
                        float o0 = v0 * cc - v1 * ss;
                        float o1 = v0 * ss + v1 * cc;
                        v0 = o0; v1 = o1;
                    }
                }
                if (OUTH) {
                    *((uint32_t*)Cv + ((size_t)row * N + col) / 2) = pack_h2(v0, v1);
                } else {
                    *(float2*)((float*)Cv + (size_t)row * N + col) = make_float2(v0, v1);
                }
            }
        }
    }
}

// ---------------------------------------------------------------------------
// Fused weight convert f32 -> half: job table passed BY VALUE (graph-safe),
// grid.y selects tensor, 8 elems/thread.
// ---------------------------------------------------------------------------
struct CvtArgs {
    const float* src[4];
    uint32_t*    dst[4];
    int          n8[4];
};

__global__ void __launch_bounds__(256) cvt_all_kernel(CvtArgs a)
{
    const int j = blockIdx.y;
    int i = blockIdx.x * 256 + threadIdx.x;
    if (i >= a.n8[j]) return;
    float4 v0 = ((const float4*)a.src[j])[2 * i];
    float4 v1 = ((const float4*)a.src[j])[2 * i + 1];
    uint4 u = make_uint4(pack_h2(v0.x, v0.y), pack_h2(v0.z, v0.w),
                         pack_h2(v1.x, v1.y), pack_h2(v1.z, v1.w));
    ((uint4*)a.dst[j])[i] = u;
}

// ---------------------------------------------------------------------------
// LayerNorm: f32 in, half out
// ---------------------------------------------------------------------------
__global__ void __launch_bounds__(256) ln_kernel(const float* __restrict__ x,
                                                 const float* __restrict__ g,
                                                 const float* __restrict__ b,
                                                 uint32_t* __restrict__ out)
{
    int row = blockIdx.x;
    int t = threadIdx.x;
    const float4* xr = (const float4*)(x + (size_t)row * HDIM);
    float4 xv = xr[t];
    float s  = xv.x + xv.y + xv.z + xv.w;
    float ss = xv.x*xv.x + xv.y*xv.y + xv.z*xv.z + xv.w*xv.w;
    #pragma unroll
    for (int o = 16; o > 0; o >>= 1) {
        s  += __shfl_xor_sync(0xffffffffu, s,  o);
        ss += __shfl_xor_sync(0xffffffffu, ss, o);
    }
    __shared__ float sred[8], ssred[8];
    if ((t & 31) == 0) { sred[t >> 5] = s; ssred[t >> 5] = ss; }
    __syncthreads();
    if (t < 32) {
        float a  = (t < 8) ? sred[t]  : 0.f;
        float a2 = (t < 8) ? ssred[t] : 0.f;
        #pragma unroll
        for (int o = 4; o > 0; o >>= 1) {
            a  += __shfl_xor_sync(0xffffffffu, a,  o);
            a2 += __shfl_xor_sync(0xffffffffu, a2, o);
        }
        if (t == 0) { sred[0] = a; ssred[0] = a2; }
    }
    __syncthreads();
    float mean = sred[0] * (1.f / HDIM);
    float var  = ssred[0] * (1.f / HDIM) - mean * mean;
    float rstd = rsqrtf(var + 1e-5f);
    float4 gv = ((const float4*)g)[t];
    float4 bv = ((const float4*)b)[t];
    float o0 = (xv.x - mean) * rstd * gv.x + bv.x;
    float o1 = (xv.y - mean) * rstd * gv.y + bv.y;
    float o2 = (xv.z - mean) * rstd * gv.z + bv.z;
    float o3 = (xv.w - mean) * rstd * gv.w + bv.w;
    uint2 u = make_uint2(pack_h2(o0, o1), pack_h2(o2, o3));
    ((uint2*)(out + (size_t)row * (HDIM / 2)))[t] = u;
}

// ---------------------------------------------------------------------------
// Flash attention, m16n8k16 fp16, ldmatrix operands, 2 q-tiles per block.
// Block: 256 q rows of one (seg, head); 8 warps, each owns rows
// (h*128 + wid*16 .. +15) for h in {0,1}. K/V fragments shared across the
// two m-tiles (each ldmatrix feeds 2 MMAs). 2-stage cp.async K/V ring.
// ---------------------------------------------------------------------------
#define SD 72                                    // halves per smem row
#define KSTAGE (64 * SD)                         // halves per K/V stage
#define ATTN_SMEM ((256 + 4 * 64) * SD * 2)      // 73728 B

__global__ void __launch_bounds__(256) fa_kernel(const __half* __restrict__ qkv,
                                                 uint32_t* __restrict__ out)
{
    extern __shared__ __half smh[];
    __half* Qs  = smh;                       // [256][SD]
    __half* Kst = smh + 256 * SD;            // 2 stages x [64][SD]
    __half* Vst = Kst + 2 * KSTAGE;          // 2 stages x [64][SD]

    const int qt   = blockIdx.x;             // 0..3 (256-row q tiles)
    const int head = blockIdx.y;
    const int seg  = blockIdx.z;
    const int tid  = threadIdx.x;
    const int wid  = tid >> 5;
    const int lane = tid & 31;
    const int lr   = lane >> 2;
    const int lc   = lane & 3;

    const int qbase = seg * LSEG + qt * 256;
    const __half* qp = qkv + (size_t)qbase * 3072 + head * 64;
    const __half* kbase = qkv + (size_t)seg * LSEG * 3072 + 1024 + head * 64;
    const __half* vbase = kbase + 1024;

    const uint32_t kBase = smem_u32(Kst);
    const uint32_t vBase = smem_u32(Vst);

    auto issue = [&](int kt, int b) {
        #pragma unroll
        for (int i = 0; i < 2; i++) {
            int f = i * 256 + tid;
            int key = f >> 3, c8 = (f & 7) * 8;
            uint32_t off = (uint32_t)(b * KSTAGE + key * SD + c8) * 2;
            cp16(kBase + off, kbase + (size_t)(kt * 64 + key) * 3072 + c8);
            cp16(vBase + off, vbase + (size_t)(kt * 64 + key) * 3072 + c8);
        }
        asm volatile("cp.async.commit_group;" ::: "memory");
    };

    issue(0, 0);

    // Stage Q: 256x64 halves, pure 16B copies (overlaps with first K/V load)
    #pragma unroll
    for (int i = 0; i < 8; i++) {
        int f = i * 256 + tid;
        int row = f >> 3, c8 = (f & 7) * 8;
        *(uint4*)&Qs[row * SD + c8] = *(const uint4*)(qp + (size_t)row * 3072 + c8);
    }
    __syncthreads();

    // Q fragments for both m-tiles
    uint32_t aq[2][4][4];
    #pragma unroll
    for (int h = 0; h < 2; h++) {
        const uint32_t qaddr = smem_u32(Qs) +
            (uint32_t)((h * 128 + wid * 16 + (lane & 15)) * SD + (lane >> 4) * 8) * 2;
        #pragma unroll
        for (int ks = 0; ks < 4; ks++)
            ldm4(aq[h][ks], qaddr + (uint32_t)(ks * 16) * 2);
    }

    const uint32_t fragOff = (uint32_t)((lane & 15) * SD + (lane >> 4) * 8) * 2;

    float O[2][8][4];
    float m[2][2], l[2][2];
    #pragma unroll
    for (int h = 0; h < 2; h++) {
        #pragma unroll
        for (int nt = 0; nt < 8; nt++)
            #pragma unroll
            for (int j = 0; j < 4; j++) O[h][nt][j] = 0.f;
        m[h][0] = m[h][1] = -1e30f;
        l[h][0] = l[h][1] = 0.f;
    }

    float s[2][8][4];

    for (int kt = 0; kt < 16; kt++) {
        if (kt + 1 < 16) {
            issue(kt + 1, (kt + 1) & 1);
            asm volatile("cp.async.wait_group 1;" ::: "memory");
        } else {
            asm volatile("cp.async.wait_group 0;" ::: "memory");
        }
        __syncthreads();

        const uint32_t stageOff = (uint32_t)((kt & 1) * KSTAGE) * 2;
        const uint32_t kFrag = kBase + stageOff + fragOff;
        const uint32_t vFrag = vBase + stageOff + fragOff;

        // S = Q @ K^T for both m-tiles; each K-fragment feeds 2 MMAs.
        #pragma unroll
        for (int h = 0; h < 2; h++)
            #pragma unroll
            for (int nt = 0; nt < 8; nt++)
                s[h][nt][0] = s[h][nt][1] = s[h][nt][2] = s[h][nt][3] = 0.f;
        #pragma unroll
        for (int ks = 0; ks < 4; ks++) {
            #pragma unroll
            for (int g = 0; g < 4; g++) {
                uint32_t t[4];
                ldm4(t, kFrag + (uint32_t)(g * 16 * SD + ks * 16) * 2);
                uint32_t b0[2] = { t[0], t[2] };
                uint32_t b1[2] = { t[1], t[3] };
                mma_f16(s[0][2 * g],     aq[0][ks], b0);
                mma_f16(s[0][2 * g + 1], aq[0][ks], b1);
                mma_f16(s[1][2 * g],     aq[1][ks], b0);
                mma_f16(s[1][2 * g + 1], aq[1][ks], b1);
            }
        }

        // Online softmax per m-tile
        #pragma unroll
        for (int h = 0; h < 2; h++) {
            #pragma unroll
            for (int nt = 0; nt < 8; nt++) {
                s[h][nt][0] *= 0.125f; s[h][nt][1] *= 0.125f;
                s[h][nt][2] *= 0.125f; s[h][nt][3] *= 0.125f;
            }
            float tm0 = -1e30f, tm1 = -1e30f;
            #pragma unroll
            for (int nt = 0; nt < 8; nt++) {
                tm0 = fmaxf(tm0, fmaxf(s[h][nt][0], s[h][nt][1]));
                tm1 = fmaxf(tm1, fmaxf(s[h][nt][2], s[h][nt][3]));
            }
            #pragma unroll
            for (int o = 1; o <= 2; o <<= 1) {
                tm0 = fmaxf(tm0, __shfl_xor_sync(0xffffffffu, tm0, o));
                tm1 = fmaxf(tm1, __shfl_xor_sync(0xffffffffu, tm1, o));
            }
            float mn0 = fmaxf(m[h][0], tm0), mn1 = fmaxf(m[h][1], tm1);
            float c0 = __expf(m[h][0] - mn0), c1 = __expf(m[h][1] - mn1);
            l[h][0] *= c0; l[h][1] *= c1;
            #pragma unroll
            for (int nt = 0; nt < 8; nt++) {
                O[h][nt][0] *= c0; O[h][nt][1] *= c0;
                O[h][nt][2] *= c1; O[h][nt][3] *= c1;
            }
            float ls0 = 0.f, ls1 = 0.f;
            #pragma unroll
            for (int nt = 0; nt < 8; nt++) {
                s[h][nt][0] = __expf(s[h][nt][0] - mn0);
                s[h][nt][1] = __expf(s[h][nt][1] - mn0);
                s[h][nt][2] = __expf(s[h][nt][2] - mn1);
                s[h][nt][3] = __expf(s[h][nt][3] - mn1);
                ls0 += s[h][nt][0] + s[h][nt][1];
                ls1 += s[h][nt][2] + s[h][nt][3];
            }
            #pragma unroll
            for (int o = 1; o <= 2; o <<= 1) {
                ls0 += __shfl_xor_sync(0xffffffffu, ls0, o);
                ls1 += __shfl_xor_sync(0xffffffffu, ls1, o);
            }
            l[h][0] += ls0; l[h][1] += ls1;
            m[h][0] = mn0; m[h][1] = mn1;
        }

        // O += P @ V : each V-fragment feeds 2 MMAs (both m-tiles).
        #pragma unroll
        for (int j = 0; j < 4; j++) {           // key-groups of 16
            uint32_t a0[4], a1[4];
            a0[0] = pack_h2(s[0][2 * j][0],     s[0][2 * j][1]);
            a0[1] = pack_h2(s[0][2 * j][2],     s[0][2 * j][3]);
            a0[2] = pack_h2(s[0][2 * j + 1][0], s[0][2 * j + 1][1]);
            a0[3] = pack_h2(s[0][2 * j + 1][2], s[0][2 * j + 1][3]);
            a1[0] = pack_h2(s[1][2 * j][0],     s[1][2 * j][1]);
            a1[1] = pack_h2(s[1][2 * j][2],     s[1][2 * j][3]);
            a1[2] = pack_h2(s[1][2 * j + 1][0], s[1][2 * j + 1][1]);
            a1[3] = pack_h2(s[1][2 * j + 1][2], s[1][2 * j + 1][3]);
            #pragma unroll
            for (int g = 0; g < 4; g++) {       // dim-groups of 16
                uint32_t t[4];
                ldm4t(t, vFrag + (uint32_t)(j * 16 * SD + g * 16) * 2);
                uint32_t b0[2] = { t[0], t[1] };
                uint32_t b1[2] = { t[2], t[3] };
                mma_f16(O[0][2 * g],     a0, b0);
                mma_f16(O[0][2 * g + 1], a0, b1);
                mma_f16(O[1][2 * g],     a1, b0);
                mma_f16(O[1][2 * g + 1], a1, b1);
            }
        }
        __syncthreads();   // protect stage reuse (2-stage ring)
    }

    // Write output for both m-tiles
    #pragma unroll
    for (int h = 0; h < 2; h++) {
        float inv0 = 1.f / l[h][0], inv1 = 1.f / l[h][1];
        const int row0 = qbase + h * 128 + wid * 16 + lr;
        uint32_t* o0 = out + ((size_t)row0 * HDIM + head * 64) / 2;
        uint32_t* o1 = o0 + 4 * HDIM;
        #pragma unroll
        for (int nt = 0; nt < 8; nt++) {
            o0[(nt * 8 + lc * 2) / 2] = pack_h2(O[h][nt][0] * inv0, O[h][nt][1] * inv0);
            o1[(nt * 8 + lc * 2) / 2] = pack_h2(O[h][nt][2] * inv1, O[h][nt][3] * inv1);
        }
    }
}

// ---------------------------------------------------------------------------
extern "C" void kernel_launch(void* const* d_in, const int* in_sizes, int n_in,
                              void* d_out, int out_size)
{
    const float* x        = (const float*)d_in[0];
    const float* wqkv     = (const float*)d_in[1];
    const float* wo       = (const float*)d_in[2];
    const float* ln0_g    = (const float*)d_in[3];
    const float* ln0_b    = (const float*)d_in[4];
    const float* ln1_g    = (const float*)d_in[5];
    const float* ln1_b    = (const float*)d_in[6];
    const float* fc0_w    = (const float*)d_in[7];
    const float* fc0_b    = (const float*)d_in[8];
    const float* fc1_w    = (const float*)d_in[9];
    const float* fc1_b    = (const float*)d_in[10];
    const float* rope_cos = (const float*)d_in[11];
    const float* rope_sin = (const float*)d_in[12];
    float* out = (float*)d_out;

    __half *h, *qkv, *attn, *h2, *mid, *wqkv_t, *wo_t, *fc0_t, *fc1_t;
    float *x1;
    cudaGetSymbolAddress((void**)&h,      g_h);
    cudaGetSymbolAddress((void**)&qkv,    g_qkv);
    cudaGetSymbolAddress((void**)&attn,   g_attn);
    cudaGetSymbolAddress((void**)&x1,     g_x1);
    cudaGetSymbolAddress((void**)&h2,     g_h2);
    cudaGetSymbolAddress((void**)&mid,    g_mid);
    cudaGetSymbolAddress((void**)&wqkv_t, g_wqkv_t);
    cudaGetSymbolAddress((void**)&wo_t,   g_wo_t);
    cudaGetSymbolAddress((void**)&fc0_t,  g_fc0_t);
    cudaGetSymbolAddress((void**)&fc1_t,  g_fc1_t);

    cudaFuncSetAttribute(fa_kernel, cudaFuncAttributeMaxDynamicSharedMemorySize, ATTN_SMEM);
    cudaFuncSetAttribute(tc_gemm<4,1>, cudaFuncAttributeMaxDynamicSharedMemorySize, GEMM_SMEM);
    cudaFuncSetAttribute(tc_gemm<1,0>, cudaFuncAttributeMaxDynamicSharedMemorySize, GEMM_SMEM);
    cudaFuncSetAttribute(tc_gemm<2,1>, cudaFuncAttributeMaxDynamicSharedMemorySize, GEMM_SMEM);
    cudaFuncSetAttribute(tc_gemm<3,0>, cudaFuncAttributeMaxDynamicSharedMemorySize, GEMM_SMEM);

    // 0. fused weight converts f32 -> half (job table passed by value)
    CvtArgs ca;
    ca.src[0] = wqkv;  ca.dst[0] = (uint32_t*)wqkv_t; ca.n8[0] = (3 * HDIM * HDIM) / 8;
    ca.src[1] = wo;    ca.dst[1] = (uint32_t*)wo_t;   ca.n8[1] = (HDIM * HDIM) / 8;
    ca.src[2] = fc0_w; ca.dst[2] = (uint32_t*)fc0_t;  ca.n8[2] = (MLPD * HDIM) / 8;
    ca.src[3] = fc1_w; ca.dst[3] = (uint32_t*)fc1_t;  ca.n8[3] = (HDIM * MLPD) / 8;
    cvt_all_kernel<<<dim3((MLPD * HDIM / 8 + 255) / 256, 4), 256>>>(ca);

    // 1. ln0 -> half
    ln_kernel<<<S_TOK, 256>>>(x, ln0_g, ln0_b, (uint32_t*)h);
    // 2. qkv = h @ wqkv^T with fused rope -> half
    tc_gemm<4,1><<<dim3(3 * HDIM / 128, S_TOK / 128), 256, GEMM_SMEM>>>(
        h, wqkv_t, qkv, nullptr, nullptr, rope_cos, rope_sin, S_TOK, 3 * HDIM, HDIM);
    // 3. attention -> half (256 q-rows per block)
    fa_kernel<<<dim3(LSEG / 256, NHEAD, NSEG), 256, ATTN_SMEM>>>(qkv, (uint32_t*)attn);
    // 4. x1 = x + attn @ wo^T -> f32
    tc_gemm<1,0><<<dim3(HDIM / 128, S_TOK / 128), 256, GEMM_SMEM>>>(
        attn, wo_t, x1, nullptr, x, nullptr, nullptr, S_TOK, HDIM, HDIM);
    // 5. ln1 -> half
    ln_kernel<<<S_TOK, 256>>>(x1, ln1_g, ln1_b, (uint32_t*)h2);
    // 6. mid = gelu(h2 @ fc0^T + b) -> half
    tc_gemm<2,1><<<dim3(MLPD / 128, S_TOK / 128), 256, GEMM_SMEM>>>(
        h2, fc0_t, mid, fc0_b, nullptr, nullptr, nullptr, S_TOK, MLPD, HDIM);
    // 7. out = x1 + mid @ fc1^T + b -> f32
    tc_gemm<3,0><<<dim3(HDIM / 128, S_TOK / 128), 256, GEMM_SMEM>>>(
        mid, fc1_t, out, fc1_b, x1, nullptr, nullptr, S_TOK, HDIM, MLPD);
}

// round 14
// speedup vs baseline: 1.0122x; 1.0122x over previous
#include <cuda_runtime.h>
#include <cuda_fp16.h>
#include <math.h>
#include <stdint.h>

// Problem constants
#define S_TOK   8192
#define HDIM    1024
#define NHEAD   16
#define HD      64
#define MLPD    4096
#define NSEG    8
#define LSEG    1024

// Scratch buffers (half-precision activations; fp32 residual spine)
__device__ __half g_h   [S_TOK * HDIM];     // ln0 out
__device__ __half g_qkv [S_TOK * 3 * HDIM]; // rope applied in epilogue
__device__ __half g_attn[S_TOK * HDIM];     // fa out
__device__ float  g_x1  [S_TOK * HDIM];     // x + attn@wo^T (f32)
__device__ __half g_h2  [S_TOK * HDIM];     // ln1 out
__device__ __half g_mid [S_TOK * MLPD];     // gelu(fc0)
// pre-converted weights (half)
__device__ __half g_wqkv_t[3 * HDIM * HDIM];
__device__ __half g_wo_t  [HDIM * HDIM];
__device__ __half g_fc0_t [MLPD * HDIM];
__device__ __half g_fc1_t [HDIM * MLPD];

__device__ __forceinline__ uint32_t smem_u32(const void* p) {
    uint32_t a;
    asm("{ .reg .u64 t; cvta.to.shared.u64 t, %1; cvt.u32.u64 %0, t; }" : "=r"(a) : "l"(p));
    return a;
}
__device__ __forceinline__ uint32_t pack_h2(float a, float b) {
    __half2 h = __float22half2_rn(make_float2(a, b));
    return *reinterpret_cast<uint32_t*>(&h);
}
__device__ __forceinline__ void mma_f16(float* d, const uint32_t* a, const uint32_t* b) {
    asm volatile(
        "mma.sync.aligned.m16n8k16.row.col.f32.f16.f16.f32 "
        "{%0,%1,%2,%3}, {%4,%5,%6,%7}, {%8,%9}, {%0,%1,%2,%3};"
        : "+f"(d[0]), "+f"(d[1]), "+f"(d[2]), "+f"(d[3])
        : "r"(a[0]), "r"(a[1]), "r"(a[2]), "r"(a[3]), "r"(b[0]), "r"(b[1]));
}
__device__ __forceinline__ void ldm4(uint32_t* r, uint32_t addr) {
    asm volatile("ldmatrix.sync.aligned.m8n8.x4.shared.b16 {%0,%1,%2,%3}, [%4];"
                 : "=r"(r[0]), "=r"(r[1]), "=r"(r[2]), "=r"(r[3]) : "r"(addr));
}
__device__ __forceinline__ void ldm4t(uint32_t* r, uint32_t addr) {
    asm volatile("ldmatrix.sync.aligned.m8n8.x4.trans.shared.b16 {%0,%1,%2,%3}, [%4];"
                 : "=r"(r[0]), "=r"(r[1]), "=r"(r[2]), "=r"(r[3]) : "r"(addr));
}
__device__ __forceinline__ void cp16(uint32_t dst, const void* src) {
    asm volatile("cp.async.cg.shared.global [%0], [%1], 16;" :: "r"(dst), "l"(src) : "memory");
}

// ---------------------------------------------------------------------------
// fp16 mma.sync GEMM: C[M,N] = A[M,K] @ B[N,K]^T (+ epilogue)
// 128x128 tile, BK=64 halves, 256 threads (2x4 warps), 64x32 warp tile.
// 3-stage cp.async ring, one __syncthreads per chunk, 2 CTAs/SM.
// EPI: 1=+res, 2=+bias+GELU, 3=+bias+res, 4=rope(cols<2048)
// OUTH: 1 -> write half, 0 -> write f32
// ---------------------------------------------------------------------------
#define STRD 72                                  // halves per smem row (144 B)
#define AOFF_B (128 * STRD * 2)                  // 18432 B
#define STAGE_BYTES (2 * 128 * STRD * 2)         // 36864 B
#define GEMM_SMEM (3 * STAGE_BYTES)              // 110592 B

template <int EPI, int OUTH>
__global__ void __launch_bounds__(256, 2)
tc_gemm(const __half* __restrict__ A, const __half* __restrict__ B,
        void* __restrict__ Cv, const float* __restrict__ bias,
        const float* __restrict__ res,
        const float* __restrict__ cosb, const float* __restrict__ sinb,
        int M, int N, int K)
{
    extern __shared__ uint32_t sm4[];
    const uint32_t smb = smem_u32(sm4);

    const int tid  = threadIdx.x;
    const int wid  = tid >> 5;
    const int lane = tid & 31;
    const int warp_m = wid >> 2;   // 0..1
    const int warp_n = wid & 3;    // 0..3
    const int lr = lane >> 2;
    const int lc = lane & 3;

    const __half* Ab = A + (size_t)blockIdx.y * 128 * K;
    const __half* Bb = B + (size_t)blockIdx.x * 128 * K;

    float acc[16][4];
    #pragma unroll
    for (int i = 0; i < 16; i++)
        #pragma unroll
        for (int j = 0; j < 4; j++) acc[i][j] = 0.f;

    const int NC = K >> 6;

    const uint32_t aFragOff = ((warp_m * 64 + (lane & 15)) * STRD + (lane >> 4) * 8) * 2;
    const uint32_t bFragOff = AOFF_B +
        ((warp_n * 32 + (lane & 15)) * STRD + (lane >> 4) * 8) * 2;

    auto issue = [&](int c, int b) {
        const int k0 = c << 6;
        const uint32_t base = smb + (uint32_t)b * STAGE_BYTES;
        #pragma unroll
        for (int i = 0; i < 4; i++) {
            int f = i * 256 + tid;                 // 0..1023
            int row = f >> 3, c16 = (f & 7) * 8;   // c16 in halves
            cp16(base + (uint32_t)(row * STRD + c16) * 2,
                 Ab + (size_t)row * K + k0 + c16);
            cp16(base + AOFF_B + (uint32_t)(row * STRD + c16) * 2,
                 Bb + (size_t)row * K + k0 + c16);
        }
        asm volatile("cp.async.commit_group;" ::: "memory");
    };

    issue(0, 0);
    issue(1, 1);

    for (int c = 0; c < NC; c++) {
        if (c + 1 < NC) {
            asm volatile("cp.async.wait_group 1;" ::: "memory");
        } else {
            asm volatile("cp.async.wait_group 0;" ::: "memory");
        }
        __syncthreads();

        if (c + 2 < NC) issue(c + 2, (c + 2) % 3);

        const uint32_t sb = smb + (uint32_t)(c % 3) * STAGE_BYTES;
        const uint32_t aB = sb + aFragOff;
        const uint32_t bB = sb + bFragOff;
        #pragma unroll
        for (int ks = 0; ks < 4; ks++) {           // 4 k-steps of 16
            uint32_t afr[4][4], bfr[4][2];
            #pragma unroll
            for (int mt = 0; mt < 4; mt++)
                ldm4(afr[mt], aB + (uint32_t)(mt * 16 * STRD + ks * 16) * 2);
            #pragma unroll
            for (int g = 0; g < 2; g++) {
                uint32_t t[4];
                ldm4(t, bB + (uint32_t)(g * 16 * STRD + ks * 16) * 2);
                bfr[2 * g][0] = t[0]; bfr[2 * g][1] = t[2];
                bfr[2 * g + 1][0] = t[1]; bfr[2 * g + 1][1] = t[3];
            }
            #pragma unroll
            for (int mt = 0; mt < 4; mt++)
                #pragma unroll
                for (int nt = 0; nt < 4; nt++)
                    mma_f16(acc[mt * 4 + nt], afr[mt], bfr[nt]);
        }
    }

    // Epilogue
    #pragma unroll
    for (int mt = 0; mt < 4; mt++) {
        #pragma unroll
        for (int h = 0; h < 2; h++) {
            int row = blockIdx.y * 128 + warp_m * 64 + mt * 16 + lr + h * 8;
            #pragma unroll
            for (int nt = 0; nt < 4; nt++) {
                int col = blockIdx.x * 128 + warp_n * 32 + nt * 8 + lc * 2;
                float v0 = acc[mt * 4 + nt][h * 2 + 0];
                float v1 = acc[mt * 4 + nt][h * 2 + 1];
                if (EPI == 2 || EPI == 3) {
                    v0 += bias[col];
                    v1 += bias[col + 1];
                }
                if (EPI == 2) {
                    v0 = 0.5f * v0 * (1.f + erff(v0 * 0.70710678118f));
                    v1 = 0.5f * v1 * (1.f + erff(v1 * 0.70710678118f));
                }
                if (EPI == 1 || EPI == 3) {
                    v0 += res[(size_t)row * N + col];
                    v1 += res[(size_t)row * N + col + 1];
                }
                if (EPI == 4) {
                    if (col < 2048) {
                        int i = (col & 63) >> 1;
                        float cc = cosb[row * 32 + i];
                        float ss = sinb[row * 32 + i];
                        float o0 = v0 * cc - v1 * ss;
                        float o1 = v0 * ss + v1 * cc;
                        v0 = o0; v1 = o1;
                    }
                }
                if (OUTH) {
                    *((uint32_t*)Cv + ((size_t)row * N + col) / 2) = pack_h2(v0, v1);
                } else {
                    *(float2*)((float*)Cv + (size_t)row * N + col) = make_float2(v0, v1);
                }
            }
        }
    }
}

// ---------------------------------------------------------------------------
// Fused weight convert f32 -> half: job table passed BY VALUE (graph-safe),
// grid.y selects tensor, 8 elems/thread.
// ---------------------------------------------------------------------------
struct CvtArgs {
    const float* src[4];
    uint32_t*    dst[4];
    int          n8[4];
};

__global__ void __launch_bounds__(256) cvt_all_kernel(CvtArgs a)
{
    const int j = blockIdx.y;
    int i = blockIdx.x * 256 + threadIdx.x;
    if (i >= a.n8[j]) return;
    float4 v0 = ((const float4*)a.src[j])[2 * i];
    float4 v1 = ((const float4*)a.src[j])[2 * i + 1];
    uint4 u = make_uint4(pack_h2(v0.x, v0.y), pack_h2(v0.z, v0.w),
                         pack_h2(v1.x, v1.y), pack_h2(v1.z, v1.w));
    ((uint4*)a.dst[j])[i] = u;
}

// ---------------------------------------------------------------------------
// LayerNorm: f32 in, half out
// ---------------------------------------------------------------------------
__global__ void __launch_bounds__(256) ln_kernel(const float* __restrict__ x,
                                                 const float* __restrict__ g,
                                                 const float* __restrict__ b,
                                                 uint32_t* __restrict__ out)
{
    int row = blockIdx.x;
    int t = threadIdx.x;
    const float4* xr = (const float4*)(x + (size_t)row * HDIM);
    float4 xv = xr[t];
    float s  = xv.x + xv.y + xv.z + xv.w;
    float ss = xv.x*xv.x + xv.y*xv.y + xv.z*xv.z + xv.w*xv.w;
    #pragma unroll
    for (int o = 16; o > 0; o >>= 1) {
        s  += __shfl_xor_sync(0xffffffffu, s,  o);
        ss += __shfl_xor_sync(0xffffffffu, ss, o);
    }
    __shared__ float sred[8], ssred[8];
    if ((t & 31) == 0) { sred[t >> 5] = s; ssred[t >> 5] = ss; }
    __syncthreads();
    if (t < 32) {
        float a  = (t < 8) ? sred[t]  : 0.f;
        float a2 = (t < 8) ? ssred[t] : 0.f;
        #pragma unroll
        for (int o = 4; o > 0; o >>= 1) {
            a  += __shfl_xor_sync(0xffffffffu, a,  o);
            a2 += __shfl_xor_sync(0xffffffffu, a2, o);
        }
        if (t == 0) { sred[0] = a; ssred[0] = a2; }
    }
    __syncthreads();
    float mean = sred[0] * (1.f / HDIM);
    float var  = ssred[0] * (1.f / HDIM) - mean * mean;
    float rstd = rsqrtf(var + 1e-5f);
    float4 gv = ((const float4*)g)[t];
    float4 bv = ((const float4*)b)[t];
    float o0 = (xv.x - mean) * rstd * gv.x + bv.x;
    float o1 = (xv.y - mean) * rstd * gv.y + bv.y;
    float o2 = (xv.z - mean) * rstd * gv.z + bv.z;
    float o3 = (xv.w - mean) * rstd * gv.w + bv.w;
    uint2 u = make_uint2(pack_h2(o0, o1), pack_h2(o2, o3));
    ((uint2*)(out + (size_t)row * (HDIM / 2)))[t] = u;
}

// ---------------------------------------------------------------------------
// Flash attention, m16n8k16 fp16, ldmatrix operands, 3-stage cp.async
// ring for K/V tiles (one __syncthreads per tile). Q pre-scaled by 1/8
// during staging (power of two: bit-exact vs scaling S).
// ---------------------------------------------------------------------------
#define SD 72                                    // halves per smem row
#define KSTAGE (64 * SD)                         // halves per K/V stage
#define ATTN_SMEM ((128 + 6 * 64) * SD * 2)      // 73728 B

__global__ void __launch_bounds__(256) fa_kernel(const __half* __restrict__ qkv,
                                                 uint32_t* __restrict__ out)
{
    extern __shared__ __half smh[];
    __half* Qs  = smh;                       // [128][SD]
    __half* Kst = smh + 128 * SD;            // 3 stages x [64][SD]
    __half* Vst = Kst + 3 * KSTAGE;          // 3 stages x [64][SD]

    const int qt   = blockIdx.x;
    const int head = blockIdx.y;
    const int seg  = blockIdx.z;
    const int tid  = threadIdx.x;
    const int wid  = tid >> 5;
    const int lane = tid & 31;
    const int lr   = lane >> 2;
    const int lc   = lane & 3;

    const int qbase = seg * LSEG + qt * 128;
    const __half* qp = qkv + (size_t)qbase * 3072 + head * 64;
    const __half* kbase = qkv + (size_t)seg * LSEG * 3072 + 1024 + head * 64;
    const __half* vbase = kbase + 1024;

    const uint32_t kBase = smem_u32(Kst);
    const uint32_t vBase = smem_u32(Vst);

    auto issue = [&](int kt, int b) {
        #pragma unroll
        for (int i = 0; i < 2; i++) {
            int f = i * 256 + tid;
            int key = f >> 3, c8 = (f & 7) * 8;
            uint32_t off = (uint32_t)(b * KSTAGE + key * SD + c8) * 2;
            cp16(kBase + off, kbase + (size_t)(kt * 64 + key) * 3072 + c8);
            cp16(vBase + off, vbase + (size_t)(kt * 64 + key) * 3072 + c8);
        }
        asm volatile("cp.async.commit_group;" ::: "memory");
    };

    issue(0, 0);
    issue(1, 1);

    // Stage Q scaled by 1/8 (exact exponent shift in fp16)
    const __half2 qscale = __float2half2_rn(0.125f);
    #pragma unroll
    for (int i = 0; i < 4; i++) {
        int f = i * 256 + tid;
        int row = f >> 3, c8 = (f & 7) * 8;
        uint4 v = *(const uint4*)(qp + (size_t)row * 3072 + c8);
        __half2* hv = (__half2*)&v;
        hv[0] = __hmul2(hv[0], qscale);
        hv[1] = __hmul2(hv[1], qscale);
        hv[2] = __hmul2(hv[2], qscale);
        hv[3] = __hmul2(hv[3], qscale);
        *(uint4*)&Qs[row * SD + c8] = v;
    }
    __syncthreads();

    // Q fragments via ldmatrix (warp rows wid*16..wid*16+15)
    uint32_t aq[4][4];
    {
        const uint32_t qaddr = smem_u32(Qs) +
            (uint32_t)((wid * 16 + (lane & 15)) * SD + (lane >> 4) * 8) * 2;
        #pragma unroll
        for (int ks = 0; ks < 4; ks++)
            ldm4(aq[ks], qaddr + (uint32_t)(ks * 16) * 2);
    }

    const uint32_t fragOff = (uint32_t)((lane & 15) * SD + (lane >> 4) * 8) * 2;

    float O[8][4];
    #pragma unroll
    for (int nt = 0; nt < 8; nt++)
        #pragma unroll
        for (int j = 0; j < 4; j++) O[nt][j] = 0.f;
    float m0 = -1e30f, m1 = -1e30f, l0 = 0.f, l1 = 0.f;

    for (int kt = 0; kt < 16; kt++) {
        if (kt + 1 < 16) {
            asm volatile("cp.async.wait_group 1;" ::: "memory");
        } else {
            asm volatile("cp.async.wait_group 0;" ::: "memory");
        }
        __syncthreads();

        if (kt + 2 < 16) issue(kt + 2, (kt + 2) % 3);

        const uint32_t stageOff = (uint32_t)((kt % 3) * KSTAGE) * 2;
        const uint32_t kFrag = kBase + stageOff + fragOff;
        const uint32_t vFrag = vBase + stageOff + fragOff;

        // S = (Q/8) @ K^T  (4 key-groups of 16 x 4 k-steps)
        float s[8][4];
        #pragma unroll
        for (int nt = 0; nt < 8; nt++)
            s[nt][0] = s[nt][1] = s[nt][2] = s[nt][3] = 0.f;
        #pragma unroll
        for (int ks = 0; ks < 4; ks++) {
            #pragma unroll
            for (int g = 0; g < 4; g++) {
                uint32_t t[4];
                ldm4(t, kFrag + (uint32_t)(g * 16 * SD + ks * 16) * 2);
                uint32_t b0[2] = { t[0], t[2] };
                uint32_t b1[2] = { t[1], t[3] };
                mma_f16(s[2 * g],     aq[ks], b0);
                mma_f16(s[2 * g + 1], aq[ks], b1);
            }
        }

        // Online softmax
        float tm0 = -1e30f, tm1 = -1e30f;
        #pragma unroll
        for (int nt = 0; nt < 8; nt++) {
            tm0 = fmaxf(tm0, fmaxf(s[nt][0], s[nt][1]));
            tm1 = fmaxf(tm1, fmaxf(s[nt][2], s[nt][3]));
        }
        #pragma unroll
        for (int o = 1; o <= 2; o <<= 1) {
            tm0 = fmaxf(tm0, __shfl_xor_sync(0xffffffffu, tm0, o));
            tm1 = fmaxf(tm1, __shfl_xor_sync(0xffffffffu, tm1, o));
        }
        float mn0 = fmaxf(m0, tm0), mn1 = fmaxf(m1, tm1);
        float c0 = __expf(m0 - mn0), c1 = __expf(m1 - mn1);
        l0 *= c0; l1 *= c1;
        #pragma unroll
        for (int nt = 0; nt < 8; nt++) {
            O[nt][0] *= c0; O[nt][1] *= c0;
            O[nt][2] *= c1; O[nt][3] *= c1;
        }
        float ls0 = 0.f, ls1 = 0.f;
        #pragma unroll
        for (int nt = 0; nt < 8; nt++) {
            s[nt][0] = __expf(s[nt][0] - mn0);
            s[nt][1] = __expf(s[nt][1] - mn0);
            s[nt][2] = __expf(s[nt][2] - mn1);
            s[nt][3] = __expf(s[nt][3] - mn1);
            ls0 += s[nt][0] + s[nt][1];
            ls1 += s[nt][2] + s[nt][3];
        }
        #pragma unroll
        for (int o = 1; o <= 2; o <<= 1) {
            ls0 += __shfl_xor_sync(0xffffffffu, ls0, o);
            ls1 += __shfl_xor_sync(0xffffffffu, ls1, o);
        }
        l0 += ls0; l1 += ls1;
        m0 = mn0; m1 = mn1;

        // O += P @ V : A from accum (layout match), B via ldmatrix.trans
        #pragma unroll
        for (int j = 0; j < 4; j++) {           // key-groups of 16
            uint32_t a[4];
            a[0] = pack_h2(s[2 * j][0],     s[2 * j][1]);
            a[1] = pack_h2(s[2 * j][2],     s[2 * j][3]);
            a[2] = pack_h2(s[2 * j + 1][0], s[2 * j + 1][1]);
            a[3] = pack_h2(s[2 * j + 1][2], s[2 * j + 1][3]);
            #pragma unroll
            for (int g = 0; g < 4; g++) {       // dim-groups of 16
                uint32_t t[4];
                ldm4t(t, vFrag + (uint32_t)(j * 16 * SD + g * 16) * 2);
                uint32_t b0[2] = { t[0], t[1] };
                uint32_t b1[2] = { t[2], t[3] };
                mma_f16(O[2 * g],     a, b0);
                mma_f16(O[2 * g + 1], a, b1);
            }
        }
    }

    float inv0 = 1.f / l0, inv1 = 1.f / l1;
    const int row0 = qbase + wid * 16 + lr;
    uint32_t* o0 = out + ((size_t)row0 * HDIM + head * 64) / 2;
    uint32_t* o1 = o0 + 4 * HDIM;
    #pragma unroll
    for (int nt = 0; nt < 8; nt++) {
        o0[(nt * 8 + lc * 2) / 2] = pack_h2(O[nt][0] * inv0, O[nt][1] * inv0);
        o1[(nt * 8 + lc * 2) / 2] = pack_h2(O[nt][2] * inv1, O[nt][3] * inv1);
    }
}

// ---------------------------------------------------------------------------
extern "C" void kernel_launch(void* const* d_in, const int* in_sizes, int n_in,
                              void* d_out, int out_size)
{
    const float* x        = (const float*)d_in[0];
    const float* wqkv     = (const float*)d_in[1];
    const float* wo       = (const float*)d_in[2];
    const float* ln0_g    = (const float*)d_in[3];
    const float* ln0_b    = (const float*)d_in[4];
    const float* ln1_g    = (const float*)d_in[5];
    const float* ln1_b    = (const float*)d_in[6];
    const float* fc0_w    = (const float*)d_in[7];
    const float* fc0_b    = (const float*)d_in[8];
    const float* fc1_w    = (const float*)d_in[9];
    const float* fc1_b    = (const float*)d_in[10];
    const float* rope_cos = (const float*)d_in[11];
    const float* rope_sin = (const float*)d_in[12];
    float* out = (float*)d_out;

    __half *h, *qkv, *attn, *h2, *mid, *wqkv_t, *wo_t, *fc0_t, *fc1_t;
    float *x1;
    cudaGetSymbolAddress((void**)&h,      g_h);
    cudaGetSymbolAddress((void**)&qkv,    g_qkv);
    cudaGetSymbolAddress((void**)&attn,   g_attn);
    cudaGetSymbolAddress((void**)&x1,     g_x1);
    cudaGetSymbolAddress((void**)&h2,     g_h2);
    cudaGetSymbolAddress((void**)&mid,    g_mid);
    cudaGetSymbolAddress((void**)&wqkv_t, g_wqkv_t);
    cudaGetSymbolAddress((void**)&wo_t,   g_wo_t);
    cudaGetSymbolAddress((void**)&fc0_t,  g_fc0_t);
    cudaGetSymbolAddress((void**)&fc1_t,  g_fc1_t);

    cudaFuncSetAttribute(fa_kernel, cudaFuncAttributeMaxDynamicSharedMemorySize, ATTN_SMEM);
    cudaFuncSetAttribute(tc_gemm<4,1>, cudaFuncAttributeMaxDynamicSharedMemorySize, GEMM_SMEM);
    cudaFuncSetAttribute(tc_gemm<1,0>, cudaFuncAttributeMaxDynamicSharedMemorySize, GEMM_SMEM);
    cudaFuncSetAttribute(tc_gemm<2,1>, cudaFuncAttributeMaxDynamicSharedMemorySize, GEMM_SMEM);
    cudaFuncSetAttribute(tc_gemm<3,0>, cudaFuncAttributeMaxDynamicSharedMemorySize, GEMM_SMEM);

    // 0. fused weight converts f32 -> half (job table passed by value)
    CvtArgs ca;
    ca.src[0] = wqkv;  ca.dst[0] = (uint32_t*)wqkv_t; ca.n8[0] = (3 * HDIM * HDIM) / 8;
    ca.src[1] = wo;    ca.dst[1] = (uint32_t*)wo_t;   ca.n8[1] = (HDIM * HDIM) / 8;
    ca.src[2] = fc0_w; ca.dst[2] = (uint32_t*)fc0_t;  ca.n8[2] = (MLPD * HDIM) / 8;
    ca.src[3] = fc1_w; ca.dst[3] = (uint32_t*)fc1_t;  ca.n8[3] = (HDIM * MLPD) / 8;
    cvt_all_kernel<<<dim3((MLPD * HDIM / 8 + 255) / 256, 4), 256>>>(ca);

    // 1. ln0 -> half
    ln_kernel<<<S_TOK, 256>>>(x, ln0_g, ln0_b, (uint32_t*)h);
    // 2. qkv = h @ wqkv^T with fused rope -> half
    tc_gemm<4,1><<<dim3(3 * HDIM / 128, S_TOK / 128), 256, GEMM_SMEM>>>(
        h, wqkv_t, qkv, nullptr, nullptr, rope_cos, rope_sin, S_TOK, 3 * HDIM, HDIM);
    // 3. attention -> half
    fa_kernel<<<dim3(LSEG / 128, NHEAD, NSEG), 256, ATTN_SMEM>>>(qkv, (uint32_t*)attn);
    // 4. x1 = x + attn @ wo^T -> f32
    tc_gemm<1,0><<<dim3(HDIM / 128, S_TOK / 128), 256, GEMM_SMEM>>>(
        attn, wo_t, x1, nullptr, x, nullptr, nullptr, S_TOK, HDIM, HDIM);
    // 5. ln1 -> half
    ln_kernel<<<S_TOK, 256>>>(x1, ln1_g, ln1_b, (uint32_t*)h2);
    // 6. mid = gelu(h2 @ fc0^T + b) -> half
    tc_gemm<2,1><<<dim3(MLPD / 128, S_TOK / 128), 256, GEMM_SMEM>>>(
        h2, fc0_t, mid, fc0_b, nullptr, nullptr, nullptr, S_TOK, MLPD, HDIM);
    // 7. out = x1 + mid @ fc1^T + b -> f32
    tc_gemm<3,0><<<dim3(HDIM / 128, S_TOK / 128), 256, GEMM_SMEM>>>(
        mid, fc1_t, out, fc1_b, x1, nullptr, nullptr, S_TOK, HDIM, MLPD);
}

// round 15
// speedup vs baseline: 1.0194x; 1.0071x over previous
#include <cuda_runtime.h>
#include <cuda_fp16.h>
#include <math.h>
#include <stdint.h>

// Problem constants
#define S_TOK   8192
#define HDIM    1024
#define NHEAD   16
#define HD      64
#define MLPD    4096
#define NSEG    8
#define LSEG    1024

// Scratch buffers (half-precision activations; fp32 residual spine)
__device__ __half g_h   [S_TOK * HDIM];     // ln0 out
__device__ __half g_qkv [S_TOK * 3 * HDIM]; // rope applied in epilogue
__device__ __half g_attn[S_TOK * HDIM];     // fa out
__device__ float  g_x1  [S_TOK * HDIM];     // x + attn@wo^T (f32)
__device__ __half g_h2  [S_TOK * HDIM];     // ln1 out
__device__ __half g_mid [S_TOK * MLPD];     // gelu(fc0)
// pre-converted weights (half)
__device__ __half g_wqkv_t[3 * HDIM * HDIM];
__device__ __half g_wo_t  [HDIM * HDIM];
__device__ __half g_fc0_t [MLPD * HDIM];
__device__ __half g_fc1_t [HDIM * MLPD];

__device__ __forceinline__ uint32_t smem_u32(const void* p) {
    uint32_t a;
    asm("{ .reg .u64 t; cvta.to.shared.u64 t, %1; cvt.u32.u64 %0, t; }" : "=r"(a) : "l"(p));
    return a;
}
__device__ __forceinline__ uint32_t pack_h2(float a, float b) {
    __half2 h = __float22half2_rn(make_float2(a, b));
    return *reinterpret_cast<uint32_t*>(&h);
}
__device__ __forceinline__ void mma_f16(float* d, const uint32_t* a, const uint32_t* b) {
    asm volatile(
        "mma.sync.aligned.m16n8k16.row.col.f32.f16.f16.f32 "
        "{%0,%1,%2,%3}, {%4,%5,%6,%7}, {%8,%9}, {%0,%1,%2,%3};"
        : "+f"(d[0]), "+f"(d[1]), "+f"(d[2]), "+f"(d[3])
        : "r"(a[0]), "r"(a[1]), "r"(a[2]), "r"(a[3]), "r"(b[0]), "r"(b[1]));
}
__device__ __forceinline__ void ldm4(uint32_t* r, uint32_t addr) {
    asm volatile("ldmatrix.sync.aligned.m8n8.x4.shared.b16 {%0,%1,%2,%3}, [%4];"
                 : "=r"(r[0]), "=r"(r[1]), "=r"(r[2]), "=r"(r[3]) : "r"(addr));
}
__device__ __forceinline__ void ldm4t(uint32_t* r, uint32_t addr) {
    asm volatile("ldmatrix.sync.aligned.m8n8.x4.trans.shared.b16 {%0,%1,%2,%3}, [%4];"
                 : "=r"(r[0]), "=r"(r[1]), "=r"(r[2]), "=r"(r[3]) : "r"(addr));
}
__device__ __forceinline__ void cp16(uint32_t dst, const void* src) {
    asm volatile("cp.async.cg.shared.global [%0], [%1], 16;" :: "r"(dst), "l"(src) : "memory");
}

// ---------------------------------------------------------------------------
// fp16 mma.sync GEMM: C[M,N] = A[M,K] @ B[N,K]^T (+ epilogue)
// 128x128 tile, BK=64 halves, 256 threads (2x4 warps), 64x32 warp tile.
// 3-stage cp.async ring, one __syncthreads per chunk, 2 CTAs/SM.
// EPI: 1=+res, 2=+bias+GELU, 3=+bias+res, 4=rope(cols<2048)
// OUTH: 1 -> write half, 0 -> write f32
// ---------------------------------------------------------------------------
#define STRD 72                                  // halves per smem row (144 B)
#define AOFF_B (128 * STRD * 2)                  // 18432 B
#define STAGE_BYTES (2 * 128 * STRD * 2)         // 36864 B
#define GEMM_SMEM (3 * STAGE_BYTES)              // 110592 B

template <int EPI, int OUTH>
__global__ void __launch_bounds__(256, 2)
tc_gemm(const __half* __restrict__ A, const __half* __restrict__ B,
        void* __restrict__ Cv, const float* __restrict__ bias,
        const float* __restrict__ res,
        const float* __restrict__ cosb, const float* __restrict__ sinb,
        int M, int N, int K)
{
    extern __shared__ uint32_t sm4[];
    const uint32_t smb = smem_u32(sm4);

    const int tid  = threadIdx.x;
    const int wid  = tid >> 5;
    const int lane = tid & 31;
    const int warp_m = wid >> 2;   // 0..1
    const int warp_n = wid & 3;    // 0..3
    const int lr = lane >> 2;
    const int lc = lane & 3;

    const __half* Ab = A + (size_t)blockIdx.y * 128 * K;
    const __half* Bb = B + (size_t)blockIdx.x * 128 * K;

    float acc[16][4];
    #pragma unroll
    for (int i = 0; i < 16; i++)
        #pragma unroll
        for (int j = 0; j < 4; j++) acc[i][j] = 0.f;

    const int NC = K >> 6;

    const uint32_t aFragOff = ((warp_m * 64 + (lane & 15)) * STRD + (lane >> 4) * 8) * 2;
    const uint32_t bFragOff = AOFF_B +
        ((warp_n * 32 + (lane & 15)) * STRD + (lane >> 4) * 8) * 2;

    auto issue = [&](int c, int b) {
        const int k0 = c << 6;
        const uint32_t base = smb + (uint32_t)b * STAGE_BYTES;
        #pragma unroll
        for (int i = 0; i < 4; i++) {
            int f = i * 256 + tid;                 // 0..1023
            int row = f >> 3, c16 = (f & 7) * 8;   // c16 in halves
            cp16(base + (uint32_t)(row * STRD + c16) * 2,
                 Ab + (size_t)row * K + k0 + c16);
            cp16(base + AOFF_B + (uint32_t)(row * STRD + c16) * 2,
                 Bb + (size_t)row * K + k0 + c16);
        }
        asm volatile("cp.async.commit_group;" ::: "memory");
    };

    issue(0, 0);
    issue(1, 1);

    for (int c = 0; c < NC; c++) {
        if (c + 1 < NC) {
            asm volatile("cp.async.wait_group 1;" ::: "memory");
        } else {
            asm volatile("cp.async.wait_group 0;" ::: "memory");
        }
        __syncthreads();

        if (c + 2 < NC) issue(c + 2, (c + 2) % 3);

        const uint32_t sb = smb + (uint32_t)(c % 3) * STAGE_BYTES;
        const uint32_t aB = sb + aFragOff;
        const uint32_t bB = sb + bFragOff;
        #pragma unroll
        for (int ks = 0; ks < 4; ks++) {           // 4 k-steps of 16
            uint32_t afr[4][4], bfr[4][2];
            #pragma unroll
            for (int mt = 0; mt < 4; mt++)
                ldm4(afr[mt], aB + (uint32_t)(mt * 16 * STRD + ks * 16) * 2);
            #pragma unroll
            for (int g = 0; g < 2; g++) {
                uint32_t t[4];
                ldm4(t, bB + (uint32_t)(g * 16 * STRD + ks * 16) * 2);
                bfr[2 * g][0] = t[0]; bfr[2 * g][1] = t[2];
                bfr[2 * g + 1][0] = t[1]; bfr[2 * g + 1][1] = t[3];
            }
            #pragma unroll
            for (int mt = 0; mt < 4; mt++)
                #pragma unroll
                for (int nt = 0; nt < 4; nt++)
                    mma_f16(acc[mt * 4 + nt], afr[mt], bfr[nt]);
        }
    }

    // Epilogue
    #pragma unroll
    for (int mt = 0; mt < 4; mt++) {
        #pragma unroll
        for (int h = 0; h < 2; h++) {
            int row = blockIdx.y * 128 + warp_m * 64 + mt * 16 + lr + h * 8;
            #pragma unroll
            for (int nt = 0; nt < 4; nt++) {
                int col = blockIdx.x * 128 + warp_n * 32 + nt * 8 + lc * 2;
                float v0 = acc[mt * 4 + nt][h * 2 + 0];
                float v1 = acc[mt * 4 + nt][h * 2 + 1];
                if (EPI == 2 || EPI == 3) {
                    v0 += bias[col];
                    v1 += bias[col + 1];
                }
                if (EPI == 2) {
                    v0 = 0.5f * v0 * (1.f + erff(v0 * 0.70710678118f));
                    v1 = 0.5f * v1 * (1.f + erff(v1 * 0.70710678118f));
                }
                if (EPI == 1 || EPI == 3) {
                    v0 += res[(size_t)row * N + col];
                    v1 += res[(size_t)row * N + col + 1];
                }
                if (EPI == 4) {
                    if (col < 2048) {
                        int i = (col & 63) >> 1;
                        float cc = cosb[row * 32 + i];
                        float ss = sinb[row * 32 + i];
                        float o0 = v0 * cc - v1 * ss;
                        float o1 = v0 * ss + v1 * cc;
                        v0 = o0; v1 = o1;
                    }
                }
                if (OUTH) {
                    *((uint32_t*)Cv + ((size_t)row * N + col) / 2) = pack_h2(v0, v1);
                } else {
                    *(float2*)((float*)Cv + (size_t)row * N + col) = make_float2(v0, v1);
                }
            }
        }
    }
}

// ---------------------------------------------------------------------------
// Weight convert f32 -> half (8 elems / thread)
// ---------------------------------------------------------------------------
__global__ void __launch_bounds__(256) cvt_kernel(const float* __restrict__ src,
                                                  uint32_t* __restrict__ dst)
{
    int i = blockIdx.x * 256 + threadIdx.x;
    float4 v0 = ((const float4*)src)[2 * i];
    float4 v1 = ((const float4*)src)[2 * i + 1];
    uint4 u = make_uint4(pack_h2(v0.x, v0.y), pack_h2(v0.z, v0.w),
                         pack_h2(v1.x, v1.y), pack_h2(v1.z, v1.w));
    ((uint4*)dst)[i] = u;
}

// ---------------------------------------------------------------------------
// LayerNorm: f32 in, half out
// ---------------------------------------------------------------------------
__global__ void __launch_bounds__(256) ln_kernel(const float* __restrict__ x,
                                                 const float* __restrict__ g,
                                                 const float* __restrict__ b,
                                                 uint32_t* __restrict__ out)
{
    int row = blockIdx.x;
    int t = threadIdx.x;
    const float4* xr = (const float4*)(x + (size_t)row * HDIM);
    float4 xv = xr[t];
    float s  = xv.x + xv.y + xv.z + xv.w;
    float ss = xv.x*xv.x + xv.y*xv.y + xv.z*xv.z + xv.w*xv.w;
    #pragma unroll
    for (int o = 16; o > 0; o >>= 1) {
        s  += __shfl_xor_sync(0xffffffffu, s,  o);
        ss += __shfl_xor_sync(0xffffffffu, ss, o);
    }
    __shared__ float sred[8], ssred[8];
    if ((t & 31) == 0) { sred[t >> 5] = s; ssred[t >> 5] = ss; }
    __syncthreads();
    if (t < 32) {
        float a  = (t < 8) ? sred[t]  : 0.f;
        float a2 = (t < 8) ? ssred[t] : 0.f;
        #pragma unroll
        for (int o = 4; o > 0; o >>= 1) {
            a  += __shfl_xor_sync(0xffffffffu, a,  o);
            a2 += __shfl_xor_sync(0xffffffffu, a2, o);
        }
        if (t == 0) { sred[0] = a; ssred[0] = a2; }
    }
    __syncthreads();
    float mean = sred[0] * (1.f / HDIM);
    float var  = ssred[0] * (1.f / HDIM) - mean * mean;
    float rstd = rsqrtf(var + 1e-5f);
    float4 gv = ((const float4*)g)[t];
    float4 bv = ((const float4*)b)[t];
    float o0 = (xv.x - mean) * rstd * gv.x + bv.x;
    float o1 = (xv.y - mean) * rstd * gv.y + bv.y;
    float o2 = (xv.z - mean) * rstd * gv.z + bv.z;
    float o3 = (xv.w - mean) * rstd * gv.w + bv.w;
    uint2 u = make_uint2(pack_h2(o0, o1), pack_h2(o2, o3));
    ((uint2*)(out + (size_t)row * (HDIM / 2)))[t] = u;
}

// ---------------------------------------------------------------------------
// Flash attention, m16n8k16 fp16, ldmatrix operands, 3-stage cp.async
// ring for K/V tiles (one __syncthreads per tile). Q pre-scaled by 1/8
// during staging (power of two: exponent-only shift in fp16).
// ---------------------------------------------------------------------------
#define SD 72                                    // halves per smem row
#define KSTAGE (64 * SD)                         // halves per K/V stage
#define ATTN_SMEM ((128 + 6 * 64) * SD * 2)      // 73728 B

__global__ void __launch_bounds__(256) fa_kernel(const __half* __restrict__ qkv,
                                                 uint32_t* __restrict__ out)
{
    extern __shared__ __half smh[];
    __half* Qs  = smh;                       // [128][SD]
    __half* Kst = smh + 128 * SD;            // 3 stages x [64][SD]
    __half* Vst = Kst + 3 * KSTAGE;          // 3 stages x [64][SD]

    const int qt   = blockIdx.x;
    const int head = blockIdx.y;
    const int seg  = blockIdx.z;
    const int tid  = threadIdx.x;
    const int wid  = tid >> 5;
    const int lane = tid & 31;
    const int lr   = lane >> 2;
    const int lc   = lane & 3;

    const int qbase = seg * LSEG + qt * 128;
    const __half* qp = qkv + (size_t)qbase * 3072 + head * 64;
    const __half* kbase = qkv + (size_t)seg * LSEG * 3072 + 1024 + head * 64;
    const __half* vbase = kbase + 1024;

    const uint32_t kBase = smem_u32(Kst);
    const uint32_t vBase = smem_u32(Vst);

    auto issue = [&](int kt, int b) {
        #pragma unroll
        for (int i = 0; i < 2; i++) {
            int f = i * 256 + tid;
            int key = f >> 3, c8 = (f & 7) * 8;
            uint32_t off = (uint32_t)(b * KSTAGE + key * SD + c8) * 2;
            cp16(kBase + off, kbase + (size_t)(kt * 64 + key) * 3072 + c8);
            cp16(vBase + off, vbase + (size_t)(kt * 64 + key) * 3072 + c8);
        }
        asm volatile("cp.async.commit_group;" ::: "memory");
    };

    issue(0, 0);
    issue(1, 1);

    // Stage Q scaled by 1/8 (exact exponent shift in fp16)
    const __half2 qscale = __float2half2_rn(0.125f);
    #pragma unroll
    for (int i = 0; i < 4; i++) {
        int f = i * 256 + tid;
        int row = f >> 3, c8 = (f & 7) * 8;
        uint4 v = *(const uint4*)(qp + (size_t)row * 3072 + c8);
        __half2* hv = (__half2*)&v;
        hv[0] = __hmul2(hv[0], qscale);
        hv[1] = __hmul2(hv[1], qscale);
        hv[2] = __hmul2(hv[2], qscale);
        hv[3] = __hmul2(hv[3], qscale);
        *(uint4*)&Qs[row * SD + c8] = v;
    }
    __syncthreads();

    // Q fragments via ldmatrix (warp rows wid*16..wid*16+15)
    uint32_t aq[4][4];
    {
        const uint32_t qaddr = smem_u32(Qs) +
            (uint32_t)((wid * 16 + (lane & 15)) * SD + (lane >> 4) * 8) * 2;
        #pragma unroll
        for (int ks = 0; ks < 4; ks++)
            ldm4(aq[ks], qaddr + (uint32_t)(ks * 16) * 2);
    }

    const uint32_t fragOff = (uint32_t)((lane & 15) * SD + (lane >> 4) * 8) * 2;

    float O[8][4];
    #pragma unroll
    for (int nt = 0; nt < 8; nt++)
        #pragma unroll
        for (int j = 0; j < 4; j++) O[nt][j] = 0.f;
    float m0 = -1e30f, m1 = -1e30f, l0 = 0.f, l1 = 0.f;

    for (int kt = 0; kt < 16; kt++) {
        if (kt + 1 < 16) {
            asm volatile("cp.async.wait_group 1;" ::: "memory");
        } else {
            asm volatile("cp.async.wait_group 0;" ::: "memory");
        }
        __syncthreads();

        if (kt + 2 < 16) issue(kt + 2, (kt + 2) % 3);

        const uint32_t stageOff = (uint32_t)((kt % 3) * KSTAGE) * 2;
        const uint32_t kFrag = kBase + stageOff + fragOff;
        const uint32_t vFrag = vBase + stageOff + fragOff;

        // S = (Q/8) @ K^T  (4 key-groups of 16 x 4 k-steps)
        float s[8][4];
        #pragma unroll
        for (int nt = 0; nt < 8; nt++)
            s[nt][0] = s[nt][1] = s[nt][2] = s[nt][3] = 0.f;
        #pragma unroll
        for (int ks = 0; ks < 4; ks++) {
            #pragma unroll
            for (int g = 0; g < 4; g++) {
                uint32_t t[4];
                ldm4(t, kFrag + (uint32_t)(g * 16 * SD + ks * 16) * 2);
                uint32_t b0[2] = { t[0], t[2] };
                uint32_t b1[2] = { t[1], t[3] };
                mma_f16(s[2 * g],     aq[ks], b0);
                mma_f16(s[2 * g + 1], aq[ks], b1);
            }
        }

        // Online softmax
        float tm0 = -1e30f, tm1 = -1e30f;
        #pragma unroll
        for (int nt = 0; nt < 8; nt++) {
            tm0 = fmaxf(tm0, fmaxf(s[nt][0], s[nt][1]));
            tm1 = fmaxf(tm1, fmaxf(s[nt][2], s[nt][3]));
        }
        #pragma unroll
        for (int o = 1; o <= 2; o <<= 1) {
            tm0 = fmaxf(tm0, __shfl_xor_sync(0xffffffffu, tm0, o));
            tm1 = fmaxf(tm1, __shfl_xor_sync(0xffffffffu, tm1, o));
        }
        float mn0 = fmaxf(m0, tm0), mn1 = fmaxf(m1, tm1);
        float c0 = __expf(m0 - mn0), c1 = __expf(m1 - mn1);
        l0 *= c0; l1 *= c1;
        #pragma unroll
        for (int nt = 0; nt < 8; nt++) {
            O[nt][0] *= c0; O[nt][1] *= c0;
            O[nt][2] *= c1; O[nt][3] *= c1;
        }
        float ls0 = 0.f, ls1 = 0.f;
        #pragma unroll
        for (int nt = 0; nt < 8; nt++) {
            s[nt][0] = __expf(s[nt][0] - mn0);
            s[nt][1] = __expf(s[nt][1] - mn0);
            s[nt][2] = __expf(s[nt][2] - mn1);
            s[nt][3] = __expf(s[nt][3] - mn1);
            ls0 += s[nt][0] + s[nt][1];
            ls1 += s[nt][2] + s[nt][3];
        }
        #pragma unroll
        for (int o = 1; o <= 2; o <<= 1) {
            ls0 += __shfl_xor_sync(0xffffffffu, ls0, o);
            ls1 += __shfl_xor_sync(0xffffffffu, ls1, o);
        }
        l0 += ls0; l1 += ls1;
        m0 = mn0; m1 = mn1;

        // O += P @ V : A from accum (layout match), B via ldmatrix.trans
        #pragma unroll
        for (int j = 0; j < 4; j++) {           // key-groups of 16
            uint32_t a[4];
            a[0] = pack_h2(s[2 * j][0],     s[2 * j][1]);
            a[1] = pack_h2(s[2 * j][2],     s[2 * j][3]);
            a[2] = pack_h2(s[2 * j + 1][0], s[2 * j + 1][1]);
            a[3] = pack_h2(s[2 * j + 1][2], s[2 * j + 1][3]);
            #pragma unroll
            for (int g = 0; g < 4; g++) {       // dim-groups of 16
                uint32_t t[4];
                ldm4t(t, vFrag + (uint32_t)(j * 16 * SD + g * 16) * 2);
                uint32_t b0[2] = { t[0], t[1] };
                uint32_t b1[2] = { t[2], t[3] };
                mma_f16(O[2 * g],     a, b0);
                mma_f16(O[2 * g + 1], a, b1);
            }
        }
    }

    float inv0 = 1.f / l0, inv1 = 1.f / l1;
    const int row0 = qbase + wid * 16 + lr;
    uint32_t* o0 = out + ((size_t)row0 * HDIM + head * 64) / 2;
    uint32_t* o1 = o0 + 4 * HDIM;
    #pragma unroll
    for (int nt = 0; nt < 8; nt++) {
        o0[(nt * 8 + lc * 2) / 2] = pack_h2(O[nt][0] * inv0, O[nt][1] * inv0);
        o1[(nt * 8 + lc * 2) / 2] = pack_h2(O[nt][2] * inv1, O[nt][3] * inv1);
    }
}

// ---------------------------------------------------------------------------
extern "C" void kernel_launch(void* const* d_in, const int* in_sizes, int n_in,
                              void* d_out, int out_size)
{
    const float* x        = (const float*)d_in[0];
    const float* wqkv     = (const float*)d_in[1];
    const float* wo       = (const float*)d_in[2];
    const float* ln0_g    = (const float*)d_in[3];
    const float* ln0_b    = (const float*)d_in[4];
    const float* ln1_g    = (const float*)d_in[5];
    const float* ln1_b    = (const float*)d_in[6];
    const float* fc0_w    = (const float*)d_in[7];
    const float* fc0_b    = (const float*)d_in[8];
    const float* fc1_w    = (const float*)d_in[9];
    const float* fc1_b    = (const float*)d_in[10];
    const float* rope_cos = (const float*)d_in[11];
    const float* rope_sin = (const float*)d_in[12];
    float* out = (float*)d_out;

    __half *h, *qkv, *attn, *h2, *mid, *wqkv_t, *wo_t, *fc0_t, *fc1_t;
    float *x1;
    cudaGetSymbolAddress((void**)&h,      g_h);
    cudaGetSymbolAddress((void**)&qkv,    g_qkv);
    cudaGetSymbolAddress((void**)&attn,   g_attn);
    cudaGetSymbolAddress((void**)&x1,     g_x1);
    cudaGetSymbolAddress((void**)&h2,     g_h2);
    cudaGetSymbolAddress((void**)&mid,    g_mid);
    cudaGetSymbolAddress((void**)&wqkv_t, g_wqkv_t);
    cudaGetSymbolAddress((void**)&wo_t,   g_wo_t);
    cudaGetSymbolAddress((void**)&fc0_t,  g_fc0_t);
    cudaGetSymbolAddress((void**)&fc1_t,  g_fc1_t);

    cudaFuncSetAttribute(fa_kernel, cudaFuncAttributeMaxDynamicSharedMemorySize, ATTN_SMEM);
    cudaFuncSetAttribute(tc_gemm<4,1>, cudaFuncAttributeMaxDynamicSharedMemorySize, GEMM_SMEM);
    cudaFuncSetAttribute(tc_gemm<1,0>, cudaFuncAttributeMaxDynamicSharedMemorySize, GEMM_SMEM);
    cudaFuncSetAttribute(tc_gemm<2,1>, cudaFuncAttributeMaxDynamicSharedMemorySize, GEMM_SMEM);
    cudaFuncSetAttribute(tc_gemm<3,0>, cudaFuncAttributeMaxDynamicSharedMemorySize, GEMM_SMEM);

    // 0. weight converts f32 -> half
    cvt_kernel<<<(3 * HDIM * HDIM) / 2048, 256>>>(wqkv, (uint32_t*)wqkv_t);
    cvt_kernel<<<(HDIM * HDIM) / 2048, 256>>>(wo, (uint32_t*)wo_t);
    cvt_kernel<<<(MLPD * HDIM) / 2048, 256>>>(fc0_w, (uint32_t*)fc0_t);
    cvt_kernel<<<(HDIM * MLPD) / 2048, 256>>>(fc1_w, (uint32_t*)fc1_t);

    // 1. ln0 -> half
    ln_kernel<<<S_TOK, 256>>>(x, ln0_g, ln0_b, (uint32_t*)h);
    // 2. qkv = h @ wqkv^T with fused rope -> half
    tc_gemm<4,1><<<dim3(3 * HDIM / 128, S_TOK / 128), 256, GEMM_SMEM>>>(
        h, wqkv_t, qkv, nullptr, nullptr, rope_cos, rope_sin, S_TOK, 3 * HDIM, HDIM);
    // 3. attention -> half
    fa_kernel<<<dim3(LSEG / 128, NHEAD, NSEG), 256, ATTN_SMEM>>>(qkv, (uint32_t*)attn);
    // 4. x1 = x + attn @ wo^T -> f32
    tc_gemm<1,0><<<dim3(HDIM / 128, S_TOK / 128), 256, GEMM_SMEM>>>(
        attn, wo_t, x1, nullptr, x, nullptr, nullptr, S_TOK, HDIM, HDIM);
    // 5. ln1 -> half
    ln_kernel<<<S_TOK, 256>>>(x1, ln1_g, ln1_b, (uint32_t*)h2);
    // 6. mid = gelu(h2 @ fc0^T + b) -> half
    tc_gemm<2,1><<<dim3(MLPD / 128, S_TOK / 128), 256, GEMM_SMEM>>>(
        h2, fc0_t, mid, fc0_b, nullptr, nullptr, nullptr, S_TOK, MLPD, HDIM);
    // 7. out = x1 + mid @ fc1^T + b -> f32
    tc_gemm<3,0><<<dim3(HDIM / 128, S_TOK / 128), 256, GEMM_SMEM>>>(
        mid, fc1_t, out, fc1_b, x1, nullptr, nullptr, S_TOK, HDIM, MLPD);
}

// round 16
// speedup vs baseline: 1.0234x; 1.0039x over previous
#include <cuda_runtime.h>
#include <cuda_fp16.h>
#include <math.h>
#include <stdint.h>

// Problem constants
#define S_TOK   8192
#define HDIM    1024
#define NHEAD   16
#define HD      64
#define MLPD    4096
#define NSEG    8
#define LSEG    1024

// Scratch buffers (half-precision activations; fp32 residual spine)
__device__ __half g_h   [S_TOK * HDIM];     // ln0 out
__device__ __half g_qkv [S_TOK * 3 * HDIM]; // rope applied in epilogue
__device__ __half g_attn[S_TOK * HDIM];     // fa out
__device__ float  g_x1  [S_TOK * HDIM];     // x + attn@wo^T (f32)
__device__ __half g_h2  [S_TOK * HDIM];     // ln1 out
__device__ __half g_mid [S_TOK * MLPD];     // gelu(fc0)
// pre-converted weights (half)
__device__ __half g_wqkv_t[3 * HDIM * HDIM];
__device__ __half g_wo_t  [HDIM * HDIM];
__device__ __half g_fc0_t [MLPD * HDIM];
__device__ __half g_fc1_t [HDIM * MLPD];

__device__ __forceinline__ uint32_t smem_u32(const void* p) {
    uint32_t a;
    asm("{ .reg .u64 t; cvta.to.shared.u64 t, %1; cvt.u32.u64 %0, t; }" : "=r"(a) : "l"(p));
    return a;
}
__device__ __forceinline__ uint32_t pack_h2(float a, float b) {
    __half2 h = __float22half2_rn(make_float2(a, b));
    return *reinterpret_cast<uint32_t*>(&h);
}
__device__ __forceinline__ void mma_f16(float* d, const uint32_t* a, const uint32_t* b) {
    asm volatile(
        "mma.sync.aligned.m16n8k16.row.col.f32.f16.f16.f32 "
        "{%0,%1,%2,%3}, {%4,%5,%6,%7}, {%8,%9}, {%0,%1,%2,%3};"
        : "+f"(d[0]), "+f"(d[1]), "+f"(d[2]), "+f"(d[3])
        : "r"(a[0]), "r"(a[1]), "r"(a[2]), "r"(a[3]), "r"(b[0]), "r"(b[1]));
}
__device__ __forceinline__ void ldm4(uint32_t* r, uint32_t addr) {
    asm volatile("ldmatrix.sync.aligned.m8n8.x4.shared.b16 {%0,%1,%2,%3}, [%4];"
                 : "=r"(r[0]), "=r"(r[1]), "=r"(r[2]), "=r"(r[3]) : "r"(addr));
}
__device__ __forceinline__ void ldm4t(uint32_t* r, uint32_t addr) {
    asm volatile("ldmatrix.sync.aligned.m8n8.x4.trans.shared.b16 {%0,%1,%2,%3}, [%4];"
                 : "=r"(r[0]), "=r"(r[1]), "=r"(r[2]), "=r"(r[3]) : "r"(addr));
}
__device__ __forceinline__ void cp16(uint32_t dst, const void* src) {
    asm volatile("cp.async.cg.shared.global [%0], [%1], 16;" :: "r"(dst), "l"(src) : "memory");
}

// ---------------------------------------------------------------------------
// fp16 mma.sync GEMM: C[M,N] = A[M,K] @ B[N,K]^T (+ epilogue)
// 128x128 tile, BK=64 halves, 256 threads (2x4 warps), 64x32 warp tile.
// 3-stage cp.async ring, one __syncthreads per chunk, 2 CTAs/SM.
// EPI: 1=+res, 2=+bias+GELU, 3=+bias+res, 4=rope(cols<2048)
// OUTH: 1 -> write half, 0 -> write f32
// ---------------------------------------------------------------------------
#define STRD 72                                  // halves per smem row (144 B)
#define AOFF_B (128 * STRD * 2)                  // 18432 B
#define STAGE_BYTES (2 * 128 * STRD * 2)         // 36864 B
#define GEMM_SMEM (3 * STAGE_BYTES)              // 110592 B

template <int EPI, int OUTH>
__global__ void __launch_bounds__(256, 2)
tc_gemm(const __half* __restrict__ A, const __half* __restrict__ B,
        void* __restrict__ Cv, const float* __restrict__ bias,
        const float* __restrict__ res,
        const float* __restrict__ cosb, const float* __restrict__ sinb,
        int M, int N, int K)
{
    extern __shared__ uint32_t sm4[];
    const uint32_t smb = smem_u32(sm4);

    const int tid  = threadIdx.x;
    const int wid  = tid >> 5;
    const int lane = tid & 31;
    const int warp_m = wid >> 2;   // 0..1
    const int warp_n = wid & 3;    // 0..3
    const int lr = lane >> 2;
    const int lc = lane & 3;

    const __half* Ab = A + (size_t)blockIdx.y * 128 * K;
    const __half* Bb = B + (size_t)blockIdx.x * 128 * K;

    float acc[16][4];
    #pragma unroll
    for (int i = 0; i < 16; i++)
        #pragma unroll
        for (int j = 0; j < 4; j++) acc[i][j] = 0.f;

    const int NC = K >> 6;

    const uint32_t aFragOff = ((warp_m * 64 + (lane & 15)) * STRD + (lane >> 4) * 8) * 2;
    const uint32_t bFragOff = AOFF_B +
        ((warp_n * 32 + (lane & 15)) * STRD + (lane >> 4) * 8) * 2;

    auto issue = [&](int c, int b) {
        const int k0 = c << 6;
        const uint32_t base = smb + (uint32_t)b * STAGE_BYTES;
        #pragma unroll
        for (int i = 0; i < 4; i++) {
            int f = i * 256 + tid;                 // 0..1023
            int row = f >> 3, c16 = (f & 7) * 8;   // c16 in halves
            cp16(base + (uint32_t)(row * STRD + c16) * 2,
                 Ab + (size_t)row * K + k0 + c16);
            cp16(base + AOFF_B + (uint32_t)(row * STRD + c16) * 2,
                 Bb + (size_t)row * K + k0 + c16);
        }
        asm volatile("cp.async.commit_group;" ::: "memory");
    };

    issue(0, 0);
    issue(1, 1);

    for (int c = 0; c < NC; c++) {
        if (c + 1 < NC) {
            asm volatile("cp.async.wait_group 1;" ::: "memory");
        } else {
            asm volatile("cp.async.wait_group 0;" ::: "memory");
        }
        __syncthreads();

        if (c + 2 < NC) issue(c + 2, (c + 2) % 3);

        const uint32_t sb = smb + (uint32_t)(c % 3) * STAGE_BYTES;
        const uint32_t aB = sb + aFragOff;
        const uint32_t bB = sb + bFragOff;
        #pragma unroll
        for (int ks = 0; ks < 4; ks++) {           // 4 k-steps of 16
            uint32_t afr[4][4], bfr[4][2];
            #pragma unroll
            for (int mt = 0; mt < 4; mt++)
                ldm4(afr[mt], aB + (uint32_t)(mt * 16 * STRD + ks * 16) * 2);
            #pragma unroll
            for (int g = 0; g < 2; g++) {
                uint32_t t[4];
                ldm4(t, bB + (uint32_t)(g * 16 * STRD + ks * 16) * 2);
                bfr[2 * g][0] = t[0]; bfr[2 * g][1] = t[2];
                bfr[2 * g + 1][0] = t[1]; bfr[2 * g + 1][1] = t[3];
            }
            #pragma unroll
            for (int mt = 0; mt < 4; mt++)
                #pragma unroll
                for (int nt = 0; nt < 4; nt++)
                    mma_f16(acc[mt * 4 + nt], afr[mt], bfr[nt]);
        }
    }

    // Epilogue
    #pragma unroll
    for (int mt = 0; mt < 4; mt++) {
        #pragma unroll
        for (int h = 0; h < 2; h++) {
            int row = blockIdx.y * 128 + warp_m * 64 + mt * 16 + lr + h * 8;
            #pragma unroll
            for (int nt = 0; nt < 4; nt++) {
                int col = blockIdx.x * 128 + warp_n * 32 + nt * 8 + lc * 2;
                float v0 = acc[mt * 4 + nt][h * 2 + 0];
                float v1 = acc[mt * 4 + nt][h * 2 + 1];
                if (EPI == 2 || EPI == 3) {
                    v0 += bias[col];
                    v1 += bias[col + 1];
                }
                if (EPI == 2) {
                    v0 = 0.5f * v0 * (1.f + erff(v0 * 0.70710678118f));
                    v1 = 0.5f * v1 * (1.f + erff(v1 * 0.70710678118f));
                }
                if (EPI == 1 || EPI == 3) {
                    v0 += res[(size_t)row * N + col];
                    v1 += res[(size_t)row * N + col + 1];
                }
                if (EPI == 4) {
                    if (col < 2048) {
                        int i = (col & 63) >> 1;
                        float cc = cosb[row * 32 + i];
                        float ss = sinb[row * 32 + i];
                        float o0 = v0 * cc - v1 * ss;
                        float o1 = v0 * ss + v1 * cc;
                        v0 = o0; v1 = o1;
                    }
                }
                if (OUTH) {
                    *((uint32_t*)Cv + ((size_t)row * N + col) / 2) = pack_h2(v0, v1);
                } else {
                    *(float2*)((float*)Cv + (size_t)row * N + col) = make_float2(v0, v1);
                }
            }
        }
    }
}

// ---------------------------------------------------------------------------
// Weight convert f32 -> half (8 elems / thread)
// ---------------------------------------------------------------------------
__global__ void __launch_bounds__(256) cvt_kernel(const float* __restrict__ src,
                                                  uint32_t* __restrict__ dst)
{
    int i = blockIdx.x * 256 + threadIdx.x;
    float4 v0 = ((const float4*)src)[2 * i];
    float4 v1 = ((const float4*)src)[2 * i + 1];
    uint4 u = make_uint4(pack_h2(v0.x, v0.y), pack_h2(v0.z, v0.w),
                         pack_h2(v1.x, v1.y), pack_h2(v1.z, v1.w));
    ((uint4*)dst)[i] = u;
}

// ---------------------------------------------------------------------------
// LayerNorm: warp-per-row, 8 rows per 256-thread block, no block barriers.
// f32 in, half out.
// ---------------------------------------------------------------------------
__global__ void __launch_bounds__(256) ln_kernel(const float* __restrict__ x,
                                                 const float* __restrict__ g,
                                                 const float* __restrict__ b,
                                                 uint32_t* __restrict__ out)
{
    const int warp = threadIdx.x >> 5;
    const int lane = threadIdx.x & 31;
    const int row  = blockIdx.x * 8 + warp;

    const float4* xr = (const float4*)(x + (size_t)row * HDIM);
    float4 v[8];
    #pragma unroll
    for (int i = 0; i < 8; i++) v[i] = xr[lane + i * 32];

    float s = 0.f, ss = 0.f;
    #pragma unroll
    for (int i = 0; i < 8; i++) {
        s  += v[i].x + v[i].y + v[i].z + v[i].w;
        ss += v[i].x * v[i].x + v[i].y * v[i].y + v[i].z * v[i].z + v[i].w * v[i].w;
    }
    #pragma unroll
    for (int o = 16; o > 0; o >>= 1) {
        s  += __shfl_xor_sync(0xffffffffu, s,  o);
        ss += __shfl_xor_sync(0xffffffffu, ss, o);
    }
    float mean = s * (1.f / HDIM);
    float var  = ss * (1.f / HDIM) - mean * mean;
    float rstd = rsqrtf(var + 1e-5f);

    uint2* orow = (uint2*)(out + (size_t)row * (HDIM / 2));
    #pragma unroll
    for (int i = 0; i < 8; i++) {
        float4 gv = ((const float4*)g)[lane + i * 32];
        float4 bv = ((const float4*)b)[lane + i * 32];
        float o0 = (v[i].x - mean) * rstd * gv.x + bv.x;
        float o1 = (v[i].y - mean) * rstd * gv.y + bv.y;
        float o2 = (v[i].z - mean) * rstd * gv.z + bv.z;
        float o3 = (v[i].w - mean) * rstd * gv.w + bv.w;
        orow[lane + i * 32] = make_uint2(pack_h2(o0, o1), pack_h2(o2, o3));
    }
}

// ---------------------------------------------------------------------------
// Flash attention, m16n8k16 fp16, ldmatrix operands, 3-stage cp.async
// ring for K/V tiles (one __syncthreads per tile). Q pre-scaled by 1/8
// during staging (power of two: exponent-only shift in fp16).
// ---------------------------------------------------------------------------
#define SD 72                                    // halves per smem row
#define KSTAGE (64 * SD)                         // halves per K/V stage
#define ATTN_SMEM ((128 + 6 * 64) * SD * 2)      // 73728 B

__global__ void __launch_bounds__(256) fa_kernel(const __half* __restrict__ qkv,
                                                 uint32_t* __restrict__ out)
{
    extern __shared__ __half smh[];
    __half* Qs  = smh;                       // [128][SD]
    __half* Kst = smh + 128 * SD;            // 3 stages x [64][SD]
    __half* Vst = Kst + 3 * KSTAGE;          // 3 stages x [64][SD]

    const int qt   = blockIdx.x;
    const int head = blockIdx.y;
    const int seg  = blockIdx.z;
    const int tid  = threadIdx.x;
    const int wid  = tid >> 5;
    const int lane = tid & 31;
    const int lr   = lane >> 2;
    const int lc   = lane & 3;

    const int qbase = seg * LSEG + qt * 128;
    const __half* qp = qkv + (size_t)qbase * 3072 + head * 64;
    const __half* kbase = qkv + (size_t)seg * LSEG * 3072 + 1024 + head * 64;
    const __half* vbase = kbase + 1024;

    const uint32_t kBase = smem_u32(Kst);
    const uint32_t vBase = smem_u32(Vst);

    auto issue = [&](int kt, int b) {
        #pragma unroll
        for (int i = 0; i < 2; i++) {
            int f = i * 256 + tid;
            int key = f >> 3, c8 = (f & 7) * 8;
            uint32_t off = (uint32_t)(b * KSTAGE + key * SD + c8) * 2;
            cp16(kBase + off, kbase + (size_t)(kt * 64 + key) * 3072 + c8);
            cp16(vBase + off, vbase + (size_t)(kt * 64 + key) * 3072 + c8);
        }
        asm volatile("cp.async.commit_group;" ::: "memory");
    };

    issue(0, 0);
    issue(1, 1);

    // Stage Q scaled by 1/8 (exact exponent shift in fp16)
    const __half2 qscale = __float2half2_rn(0.125f);
    #pragma unroll
    for (int i = 0; i < 4; i++) {
        int f = i * 256 + tid;
        int row = f >> 3, c8 = (f & 7) * 8;
        uint4 v = *(const uint4*)(qp + (size_t)row * 3072 + c8);
        __half2* hv = (__half2*)&v;
        hv[0] = __hmul2(hv[0], qscale);
        hv[1] = __hmul2(hv[1], qscale);
        hv[2] = __hmul2(hv[2], qscale);
        hv[3] = __hmul2(hv[3], qscale);
        *(uint4*)&Qs[row * SD + c8] = v;
    }
    __syncthreads();

    // Q fragments via ldmatrix (warp rows wid*16..wid*16+15)
    uint32_t aq[4][4];
    {
        const uint32_t qaddr = smem_u32(Qs) +
            (uint32_t)((wid * 16 + (lane & 15)) * SD + (lane >> 4) * 8) * 2;
        #pragma unroll
        for (int ks = 0; ks < 4; ks++)
            ldm4(aq[ks], qaddr + (uint32_t)(ks * 16) * 2);
    }

    const uint32_t fragOff = (uint32_t)((lane & 15) * SD + (lane >> 4) * 8) * 2;

    float O[8][4];
    #pragma unroll
    for (int nt = 0; nt < 8; nt++)
        #pragma unroll
        for (int j = 0; j < 4; j++) O[nt][j] = 0.f;
    float m0 = -1e30f, m1 = -1e30f, l0 = 0.f, l1 = 0.f;

    for (int kt = 0; kt < 16; kt++) {
        if (kt + 1 < 16) {
            asm volatile("cp.async.wait_group 1;" ::: "memory");
        } else {
            asm volatile("cp.async.wait_group 0;" ::: "memory");
        }
        __syncthreads();

        if (kt + 2 < 16) issue(kt + 2, (kt + 2) % 3);

        const uint32_t stageOff = (uint32_t)((kt % 3) * KSTAGE) * 2;
        const uint32_t kFrag = kBase + stageOff + fragOff;
        const uint32_t vFrag = vBase + stageOff + fragOff;

        // S = (Q/8) @ K^T  (4 key-groups of 16 x 4 k-steps)
        float s[8][4];
        #pragma unroll
        for (int nt = 0; nt < 8; nt++)
            s[nt][0] = s[nt][1] = s[nt][2] = s[nt][3] = 0.f;
        #pragma unroll
        for (int ks = 0; ks < 4; ks++) {
            #pragma unroll
            for (int g = 0; g < 4; g++) {
                uint32_t t[4];
                ldm4(t, kFrag + (uint32_t)(g * 16 * SD + ks * 16) * 2);
                uint32_t b0[2] = { t[0], t[2] };
                uint32_t b1[2] = { t[1], t[3] };
                mma_f16(s[2 * g],     aq[ks], b0);
                mma_f16(s[2 * g + 1], aq[ks], b1);
            }
        }

        // Online softmax
        float tm0 = -1e30f, tm1 = -1e30f;
        #pragma unroll
        for (int nt = 0; nt < 8; nt++) {
            tm0 = fmaxf(tm0, fmaxf(s[nt][0], s[nt][1]));
            tm1 = fmaxf(tm1, fmaxf(s[nt][2], s[nt][3]));
        }
        #pragma unroll
        for (int o = 1; o <= 2; o <<= 1) {
            tm0 = fmaxf(tm0, __shfl_xor_sync(0xffffffffu, tm0, o));
            tm1 = fmaxf(tm1, __shfl_xor_sync(0xffffffffu, tm1, o));
        }
        float mn0 = fmaxf(m0, tm0), mn1 = fmaxf(m1, tm1);
        float c0 = __expf(m0 - mn0), c1 = __expf(m1 - mn1);
        l0 *= c0; l1 *= c1;
        #pragma unroll
        for (int nt = 0; nt < 8; nt++) {
            O[nt][0] *= c0; O[nt][1] *= c0;
            O[nt][2] *= c1; O[nt][3] *= c1;
        }
        float ls0 = 0.f, ls1 = 0.f;
        #pragma unroll
        for (int nt = 0; nt < 8; nt++) {
            s[nt][0] = __expf(s[nt][0] - mn0);
            s[nt][1] = __expf(s[nt][1] - mn0);
            s[nt][2] = __expf(s[nt][2] - mn1);
            s[nt][3] = __expf(s[nt][3] - mn1);
            ls0 += s[nt][0] + s[nt][1];
            ls1 += s[nt][2] + s[nt][3];
        }
        #pragma unroll
        for (int o = 1; o <= 2; o <<= 1) {
            ls0 += __shfl_xor_sync(0xffffffffu, ls0, o);
            ls1 += __shfl_xor_sync(0xffffffffu, ls1, o);
        }
        l0 += ls0; l1 += ls1;
        m0 = mn0; m1 = mn1;

        // O += P @ V : A from accum (layout match), B via ldmatrix.trans
        #pragma unroll
        for (int j = 0; j < 4; j++) {           // key-groups of 16
            uint32_t a[4];
            a[0] = pack_h2(s[2 * j][0],     s[2 * j][1]);
            a[1] = pack_h2(s[2 * j][2],     s[2 * j][3]);
            a[2] = pack_h2(s[2 * j + 1][0], s[2 * j + 1][1]);
            a[3] = pack_h2(s[2 * j + 1][2], s[2 * j + 1][3]);
            #pragma unroll
            for (int g = 0; g < 4; g++) {       // dim-groups of 16
                uint32_t t[4];
                ldm4t(t, vFrag + (uint32_t)(j * 16 * SD + g * 16) * 2);
                uint32_t b0[2] = { t[0], t[1] };
                uint32_t b1[2] = { t[2], t[3] };
                mma_f16(O[2 * g],     a, b0);
                mma_f16(O[2 * g + 1], a, b1);
            }
        }
    }

    float inv0 = 1.f / l0, inv1 = 1.f / l1;
    const int row0 = qbase + wid * 16 + lr;
    uint32_t* o0 = out + ((size_t)row0 * HDIM + head * 64) / 2;
    uint32_t* o1 = o0 + 4 * HDIM;
    #pragma unroll
    for (int nt = 0; nt < 8; nt++) {
        o0[(nt * 8 + lc * 2) / 2] = pack_h2(O[nt][0] * inv0, O[nt][1] * inv0);
        o1[(nt * 8 + lc * 2) / 2] = pack_h2(O[nt][2] * inv1, O[nt][3] * inv1);
    }
}

// ---------------------------------------------------------------------------
extern "C" void kernel_launch(void* const* d_in, const int* in_sizes, int n_in,
                              void* d_out, int out_size)
{
    const float* x        = (const float*)d_in[0];
    const float* wqkv     = (const float*)d_in[1];
    const float* wo       = (const float*)d_in[2];
    const float* ln0_g    = (const float*)d_in[3];
    const float* ln0_b    = (const float*)d_in[4];
    const float* ln1_g    = (const float*)d_in[5];
    const float* ln1_b    = (const float*)d_in[6];
    const float* fc0_w    = (const float*)d_in[7];
    const float* fc0_b    = (const float*)d_in[8];
    const float* fc1_w    = (const float*)d_in[9];
    const float* fc1_b    = (const float*)d_in[10];
    const float* rope_cos = (const float*)d_in[11];
    const float* rope_sin = (const float*)d_in[12];
    float* out = (float*)d_out;

    __half *h, *qkv, *attn, *h2, *mid, *wqkv_t, *wo_t, *fc0_t, *fc1_t;
    float *x1;
    cudaGetSymbolAddress((void**)&h,      g_h);
    cudaGetSymbolAddress((void**)&qkv,    g_qkv);
    cudaGetSymbolAddress((void**)&attn,   g_attn);
    cudaGetSymbolAddress((void**)&x1,     g_x1);
    cudaGetSymbolAddress((void**)&h2,     g_h2);
    cudaGetSymbolAddress((void**)&mid,    g_mid);
    cudaGetSymbolAddress((void**)&wqkv_t, g_wqkv_t);
    cudaGetSymbolAddress((void**)&wo_t,   g_wo_t);
    cudaGetSymbolAddress((void**)&fc0_t,  g_fc0_t);
    cudaGetSymbolAddress((void**)&fc1_t,  g_fc1_t);

    cudaFuncSetAttribute(fa_kernel, cudaFuncAttributeMaxDynamicSharedMemorySize, ATTN_SMEM);
    cudaFuncSetAttribute(tc_gemm<4,1>, cudaFuncAttributeMaxDynamicSharedMemorySize, GEMM_SMEM);
    cudaFuncSetAttribute(tc_gemm<1,0>, cudaFuncAttributeMaxDynamicSharedMemorySize, GEMM_SMEM);
    cudaFuncSetAttribute(tc_gemm<2,1>, cudaFuncAttributeMaxDynamicSharedMemorySize, GEMM_SMEM);
    cudaFuncSetAttribute(tc_gemm<3,0>, cudaFuncAttributeMaxDynamicSharedMemorySize, GEMM_SMEM);

    // 0. weight converts f32 -> half
    cvt_kernel<<<(3 * HDIM * HDIM) / 2048, 256>>>(wqkv, (uint32_t*)wqkv_t);
    cvt_kernel<<<(HDIM * HDIM) / 2048, 256>>>(wo, (uint32_t*)wo_t);
    cvt_kernel<<<(MLPD * HDIM) / 2048, 256>>>(fc0_w, (uint32_t*)fc0_t);
    cvt_kernel<<<(HDIM * MLPD) / 2048, 256>>>(fc1_w, (uint32_t*)fc1_t);

    // 1. ln0 -> half
    ln_kernel<<<S_TOK / 8, 256>>>(x, ln0_g, ln0_b, (uint32_t*)h);
    // 2. qkv = h @ wqkv^T with fused rope -> half
    tc_gemm<4,1><<<dim3(3 * HDIM / 128, S_TOK / 128), 256, GEMM_SMEM>>>(
        h, wqkv_t, qkv, nullptr, nullptr, rope_cos, rope_sin, S_TOK, 3 * HDIM, HDIM);
    // 3. attention -> half
    fa_kernel<<<dim3(LSEG / 128, NHEAD, NSEG), 256, ATTN_SMEM>>>(qkv, (uint32_t*)attn);
    // 4. x1 = x + attn @ wo^T -> f32
    tc_gemm<1,0><<<dim3(HDIM / 128, S_TOK / 128), 256, GEMM_SMEM>>>(
        attn, wo_t, x1, nullptr, x, nullptr, nullptr, S_TOK, HDIM, HDIM);
    // 5. ln1 -> half
    ln_kernel<<<S_TOK / 8, 256>>>(x1, ln1_g, ln1_b, (uint32_t*)h2);
    // 6. mid = gelu(h2 @ fc0^T + b) -> half
    tc_gemm<2,1><<<dim3(MLPD / 128, S_TOK / 128), 256, GEMM_SMEM>>>(
        h2, fc0_t, mid, fc0_b, nullptr, nullptr, nullptr, S_TOK, MLPD, HDIM);
    // 7. out = x1 + mid @ fc1^T + b -> f32
    tc_gemm<3,0><<<dim3(HDIM / 128, S_TOK / 128), 256, GEMM_SMEM>>>(
        mid, fc1_t, out, fc1_b, x1, nullptr, nullptr, S_TOK, HDIM, MLPD);
}

// round 17
// speedup vs baseline: 1.0308x; 1.0073x over previous
#include <cuda_runtime.h>
#include <cuda_fp16.h>
#include <math.h>
#include <stdint.h>

// Problem constants
#define S_TOK   8192
#define HDIM    1024
#define NHEAD   16
#define HD      64
#define MLPD    4096
#define NSEG    8
#define LSEG    1024

// Scratch buffers (half-precision activations; fp32 residual spine)
__device__ __half g_h   [S_TOK * HDIM];     // ln0 out
__device__ __half g_qkv [S_TOK * 3 * HDIM]; // rope applied in epilogue
__device__ __half g_attn[S_TOK * HDIM];     // fa out
__device__ float  g_x1  [S_TOK * HDIM];     // x + attn@wo^T (f32)
__device__ __half g_h2  [S_TOK * HDIM];     // ln1 out
__device__ __half g_mid [S_TOK * MLPD];     // gelu(fc0)
// pre-converted weights (half)
__device__ __half g_wqkv_t[3 * HDIM * HDIM];
__device__ __half g_wo_t  [HDIM * HDIM];
__device__ __half g_fc0_t [MLPD * HDIM];
__device__ __half g_fc1_t [HDIM * MLPD];

__device__ __forceinline__ uint32_t smem_u32(const void* p) {
    uint32_t a;
    asm("{ .reg .u64 t; cvta.to.shared.u64 t, %1; cvt.u32.u64 %0, t; }" : "=r"(a) : "l"(p));
    return a;
}
__device__ __forceinline__ uint32_t pack_h2(float a, float b) {
    __half2 h = __float22half2_rn(make_float2(a, b));
    return *reinterpret_cast<uint32_t*>(&h);
}
__device__ __forceinline__ void mma_f16(float* d, const uint32_t* a, const uint32_t* b) {
    asm volatile(
        "mma.sync.aligned.m16n8k16.row.col.f32.f16.f16.f32 "
        "{%0,%1,%2,%3}, {%4,%5,%6,%7}, {%8,%9}, {%0,%1,%2,%3};"
        : "+f"(d[0]), "+f"(d[1]), "+f"(d[2]), "+f"(d[3])
        : "r"(a[0]), "r"(a[1]), "r"(a[2]), "r"(a[3]), "r"(b[0]), "r"(b[1]));
}
__device__ __forceinline__ void ldm4(uint32_t* r, uint32_t addr) {
    asm volatile("ldmatrix.sync.aligned.m8n8.x4.shared.b16 {%0,%1,%2,%3}, [%4];"
                 : "=r"(r[0]), "=r"(r[1]), "=r"(r[2]), "=r"(r[3]) : "r"(addr));
}
__device__ __forceinline__ void ldm4t(uint32_t* r, uint32_t addr) {
    asm volatile("ldmatrix.sync.aligned.m8n8.x4.trans.shared.b16 {%0,%1,%2,%3}, [%4];"
                 : "=r"(r[0]), "=r"(r[1]), "=r"(r[2]), "=r"(r[3]) : "r"(addr));
}
__device__ __forceinline__ void cp16(uint32_t dst, const void* src) {
    asm volatile("cp.async.cg.shared.global [%0], [%1], 16;" :: "r"(dst), "l"(src) : "memory");
}

// ---------------------------------------------------------------------------
// fp16 mma.sync GEMM: C[M,N] = A[M,K] @ B[N,K]^T (+ epilogue)
// 128x128 tile, BK=64 halves, 256 threads (2x4 warps), 64x32 warp tile.
// 3-stage cp.async ring, one __syncthreads per chunk, 2 CTAs/SM.
// EPI: 1=+res, 2=+bias+GELU, 3=+bias+res, 4=rope(cols<2048)
// OUTH: 1 -> write half, 0 -> write f32
// ---------------------------------------------------------------------------
#define STRD 72                                  // halves per smem row (144 B)
#define AOFF_B (128 * STRD * 2)                  // 18432 B
#define STAGE_BYTES (2 * 128 * STRD * 2)         // 36864 B
#define GEMM_SMEM (3 * STAGE_BYTES)              // 110592 B

template <int EPI, int OUTH>
__global__ void __launch_bounds__(256, 2)
tc_gemm(const __half* __restrict__ A, const __half* __restrict__ B,
        void* __restrict__ Cv, const float* __restrict__ bias,
        const float* __restrict__ res,
        const float* __restrict__ cosb, const float* __restrict__ sinb,
        int M, int N, int K)
{
    extern __shared__ uint32_t sm4[];
    const uint32_t smb = smem_u32(sm4);

    const int tid  = threadIdx.x;
    const int wid  = tid >> 5;
    const int lane = tid & 31;
    const int warp_m = wid >> 2;   // 0..1
    const int warp_n = wid & 3;    // 0..3
    const int lr = lane >> 2;
    const int lc = lane & 3;

    const __half* Ab = A + (size_t)blockIdx.y * 128 * K;
    const __half* Bb = B + (size_t)blockIdx.x * 128 * K;

    float acc[16][4];
    #pragma unroll
    for (int i = 0; i < 16; i++)
        #pragma unroll
        for (int j = 0; j < 4; j++) acc[i][j] = 0.f;

    const int NC = K >> 6;

    const uint32_t aFragOff = ((warp_m * 64 + (lane & 15)) * STRD + (lane >> 4) * 8) * 2;
    const uint32_t bFragOff = AOFF_B +
        ((warp_n * 32 + (lane & 15)) * STRD + (lane >> 4) * 8) * 2;

    auto issue = [&](int c, int b) {
        const int k0 = c << 6;
        const uint32_t base = smb + (uint32_t)b * STAGE_BYTES;
        #pragma unroll
        for (int i = 0; i < 4; i++) {
            int f = i * 256 + tid;                 // 0..1023
            int row = f >> 3, c16 = (f & 7) * 8;   // c16 in halves
            cp16(base + (uint32_t)(row * STRD + c16) * 2,
                 Ab + (size_t)row * K + k0 + c16);
            cp16(base + AOFF_B + (uint32_t)(row * STRD + c16) * 2,
                 Bb + (size_t)row * K + k0 + c16);
        }
        asm volatile("cp.async.commit_group;" ::: "memory");
    };

    issue(0, 0);
    issue(1, 1);

    for (int c = 0; c < NC; c++) {
        if (c + 1 < NC) {
            asm volatile("cp.async.wait_group 1;" ::: "memory");
        } else {
            asm volatile("cp.async.wait_group 0;" ::: "memory");
        }
        __syncthreads();

        if (c + 2 < NC) issue(c + 2, (c + 2) % 3);

        const uint32_t sb = smb + (uint32_t)(c % 3) * STAGE_BYTES;
        const uint32_t aB = sb + aFragOff;
        const uint32_t bB = sb + bFragOff;
        #pragma unroll
        for (int ks = 0; ks < 4; ks++) {           // 4 k-steps of 16
            uint32_t afr[4][4], bfr[4][2];
            #pragma unroll
            for (int mt = 0; mt < 4; mt++)
                ldm4(afr[mt], aB + (uint32_t)(mt * 16 * STRD + ks * 16) * 2);
            #pragma unroll
            for (int g = 0; g < 2; g++) {
                uint32_t t[4];
                ldm4(t, bB + (uint32_t)(g * 16 * STRD + ks * 16) * 2);
                bfr[2 * g][0] = t[0]; bfr[2 * g][1] = t[2];
                bfr[2 * g + 1][0] = t[1]; bfr[2 * g + 1][1] = t[3];
            }
            #pragma unroll
            for (int mt = 0; mt < 4; mt++)
                #pragma unroll
                for (int nt = 0; nt < 4; nt++)
                    mma_f16(acc[mt * 4 + nt], afr[mt], bfr[nt]);
        }
    }

    // Epilogue
    #pragma unroll
    for (int mt = 0; mt < 4; mt++) {
        #pragma unroll
        for (int h = 0; h < 2; h++) {
            int row = blockIdx.y * 128 + warp_m * 64 + mt * 16 + lr + h * 8;
            #pragma unroll
            for (int nt = 0; nt < 4; nt++) {
                int col = blockIdx.x * 128 + warp_n * 32 + nt * 8 + lc * 2;
                float v0 = acc[mt * 4 + nt][h * 2 + 0];
                float v1 = acc[mt * 4 + nt][h * 2 + 1];
                if (EPI == 2 || EPI == 3) {
                    v0 += bias[col];
                    v1 += bias[col + 1];
                }
                if (EPI == 2) {
                    v0 = 0.5f * v0 * (1.f + erff(v0 * 0.70710678118f));
                    v1 = 0.5f * v1 * (1.f + erff(v1 * 0.70710678118f));
                }
                if (EPI == 1 || EPI == 3) {
                    v0 += res[(size_t)row * N + col];
                    v1 += res[(size_t)row * N + col + 1];
                }
                if (EPI == 4) {
                    if (col < 2048) {
                        int i = (col & 63) >> 1;
                        float cc = cosb[row * 32 + i];
                        float ss = sinb[row * 32 + i];
                        float o0 = v0 * cc - v1 * ss;
                        float o1 = v0 * ss + v1 * cc;
                        v0 = o0; v1 = o1;
                    }
                }
                if (OUTH) {
                    *((uint32_t*)Cv + ((size_t)row * N + col) / 2) = pack_h2(v0, v1);
                } else {
                    *(float2*)((float*)Cv + (size_t)row * N + col) = make_float2(v0, v1);
                }
            }
        }
    }
}

// ---------------------------------------------------------------------------
// Single-launch weight convert f32 -> half: flat 8-elem index space over
// all 4 tensors, exact block count (no wasted blocks), 2-3 compares/thread.
// Boundaries in 8-elem units: wqkv 393216 | wo 131072 | fc0 524288 | fc1 524288
// ---------------------------------------------------------------------------
#define CVT_B0 393216                    // end of wqkv
#define CVT_B1 524288                    // end of wo
#define CVT_B2 1048576                   // end of fc0
#define CVT_TOTAL 1572864                // end of fc1
#define CVT_BLOCKS (CVT_TOTAL / 256)     // 6144

__global__ void __launch_bounds__(256) cvt_all_kernel(const float* __restrict__ wqkv,
                                                      const float* __restrict__ wo,
                                                      const float* __restrict__ fc0,
                                                      const float* __restrict__ fc1,
                                                      uint32_t* __restrict__ d_wqkv,
                                                      uint32_t* __restrict__ d_wo,
                                                      uint32_t* __restrict__ d_fc0,
                                                      uint32_t* __restrict__ d_fc1)
{
    int i = blockIdx.x * 256 + threadIdx.x;     // 8-elem unit index
    const float* src;
    uint32_t* dst;
    int off;
    if (i < CVT_B0)      { src = wqkv; dst = d_wqkv; off = i; }
    else if (i < CVT_B1) { src = wo;   dst = d_wo;   off = i - CVT_B0; }
    else if (i < CVT_B2) { src = fc0;  dst = d_fc0;  off = i - CVT_B1; }
    else                 { src = fc1;  dst = d_fc1;  off = i - CVT_B2; }
    float4 v0 = ((const float4*)src)[2 * off];
    float4 v1 = ((const float4*)src)[2 * off + 1];
    uint4 u = make_uint4(pack_h2(v0.x, v0.y), pack_h2(v0.z, v0.w),
                         pack_h2(v1.x, v1.y), pack_h2(v1.z, v1.w));
    ((uint4*)dst)[off] = u;
}

// ---------------------------------------------------------------------------
// LayerNorm: warp-per-row, 8 rows per 256-thread block, no block barriers.
// f32 in, half out.
// ---------------------------------------------------------------------------
__global__ void __launch_bounds__(256) ln_kernel(const float* __restrict__ x,
                                                 const float* __restrict__ g,
                                                 const float* __restrict__ b,
                                                 uint32_t* __restrict__ out)
{
    const int warp = threadIdx.x >> 5;
    const int lane = threadIdx.x & 31;
    const int row  = blockIdx.x * 8 + warp;

    const float4* xr = (const float4*)(x + (size_t)row * HDIM);
    float4 v[8];
    #pragma unroll
    for (int i = 0; i < 8; i++) v[i] = xr[lane + i * 32];

    float s = 0.f, ss = 0.f;
    #pragma unroll
    for (int i = 0; i < 8; i++) {
        s  += v[i].x + v[i].y + v[i].z + v[i].w;
        ss += v[i].x * v[i].x + v[i].y * v[i].y + v[i].z * v[i].z + v[i].w * v[i].w;
    }
    #pragma unroll
    for (int o = 16; o > 0; o >>= 1) {
        s  += __shfl_xor_sync(0xffffffffu, s,  o);
        ss += __shfl_xor_sync(0xffffffffu, ss, o);
    }
    float mean = s * (1.f / HDIM);
    float var  = ss * (1.f / HDIM) - mean * mean;
    float rstd = rsqrtf(var + 1e-5f);

    uint2* orow = (uint2*)(out + (size_t)row * (HDIM / 2));
    #pragma unroll
    for (int i = 0; i < 8; i++) {
        float4 gv = ((const float4*)g)[lane + i * 32];
        float4 bv = ((const float4*)b)[lane + i * 32];
        float o0 = (v[i].x - mean) * rstd * gv.x + bv.x;
        float o1 = (v[i].y - mean) * rstd * gv.y + bv.y;
        float o2 = (v[i].z - mean) * rstd * gv.z + bv.z;
        float o3 = (v[i].w - mean) * rstd * gv.w + bv.w;
        orow[lane + i * 32] = make_uint2(pack_h2(o0, o1), pack_h2(o2, o3));
    }
}

// ---------------------------------------------------------------------------
// Flash attention, m16n8k16 fp16, ldmatrix operands, 3-stage cp.async
// ring for K/V tiles (one __syncthreads per tile). Q pre-scaled by 1/8
// during staging (power of two: exponent-only shift in fp16).
// ---------------------------------------------------------------------------
#define SD 72                                    // halves per smem row
#define KSTAGE (64 * SD)                         // halves per K/V stage
#define ATTN_SMEM ((128 + 6 * 64) * SD * 2)      // 73728 B

__global__ void __launch_bounds__(256) fa_kernel(const __half* __restrict__ qkv,
                                                 uint32_t* __restrict__ out)
{
    extern __shared__ __half smh[];
    __half* Qs  = smh;                       // [128][SD]
    __half* Kst = smh + 128 * SD;            // 3 stages x [64][SD]
    __half* Vst = Kst + 3 * KSTAGE;          // 3 stages x [64][SD]

    const int qt   = blockIdx.x;
    const int head = blockIdx.y;
    const int seg  = blockIdx.z;
    const int tid  = threadIdx.x;
    const int wid  = tid >> 5;
    const int lane = tid & 31;
    const int lr   = lane >> 2;
    const int lc   = lane & 3;

    const int qbase = seg * LSEG + qt * 128;
    const __half* qp = qkv + (size_t)qbase * 3072 + head * 64;
    const __half* kbase = qkv + (size_t)seg * LSEG * 3072 + 1024 + head * 64;
    const __half* vbase = kbase + 1024;

    const uint32_t kBase = smem_u32(Kst);
    const uint32_t vBase = smem_u32(Vst);

    auto issue = [&](int kt, int b) {
        #pragma unroll
        for (int i = 0; i < 2; i++) {
            int f = i * 256 + tid;
            int key = f >> 3, c8 = (f & 7) * 8;
            uint32_t off = (uint32_t)(b * KSTAGE + key * SD + c8) * 2;
            cp16(kBase + off, kbase + (size_t)(kt * 64 + key) * 3072 + c8);
            cp16(vBase + off, vbase + (size_t)(kt * 64 + key) * 3072 + c8);
        }
        asm volatile("cp.async.commit_group;" ::: "memory");
    };

    issue(0, 0);
    issue(1, 1);

    // Stage Q scaled by 1/8 (exact exponent shift in fp16)
    const __half2 qscale = __float2half2_rn(0.125f);
    #pragma unroll
    for (int i = 0; i < 4; i++) {
        int f = i * 256 + tid;
        int row = f >> 3, c8 = (f & 7) * 8;
        uint4 v = *(const uint4*)(qp + (size_t)row * 3072 + c8);
        __half2* hv = (__half2*)&v;
        hv[0] = __hmul2(hv[0], qscale);
        hv[1] = __hmul2(hv[1], qscale);
        hv[2] = __hmul2(hv[2], qscale);
        hv[3] = __hmul2(hv[3], qscale);
        *(uint4*)&Qs[row * SD + c8] = v;
    }
    __syncthreads();

    // Q fragments via ldmatrix (warp rows wid*16..wid*16+15)
    uint32_t aq[4][4];
    {
        const uint32_t qaddr = smem_u32(Qs) +
            (uint32_t)((wid * 16 + (lane & 15)) * SD + (lane >> 4) * 8) * 2;
        #pragma unroll
        for (int ks = 0; ks < 4; ks++)
            ldm4(aq[ks], qaddr + (uint32_t)(ks * 16) * 2);
    }

    const uint32_t fragOff = (uint32_t)((lane & 15) * SD + (lane >> 4) * 8) * 2;

    float O[8][4];
    #pragma unroll
    for (int nt = 0; nt < 8; nt++)
        #pragma unroll
        for (int j = 0; j < 4; j++) O[nt][j] = 0.f;
    float m0 = -1e30f, m1 = -1e30f, l0 = 0.f, l1 = 0.f;

    for (int kt = 0; kt < 16; kt++) {
        if (kt + 1 < 16) {
            asm volatile("cp.async.wait_group 1;" ::: "memory");
        } else {
            asm volatile("cp.async.wait_group 0;" ::: "memory");
        }
        __syncthreads();

        if (kt + 2 < 16) issue(kt + 2, (kt + 2) % 3);

        const uint32_t stageOff = (uint32_t)((kt % 3) * KSTAGE) * 2;
        const uint32_t kFrag = kBase + stageOff + fragOff;
        const uint32_t vFrag = vBase + stageOff + fragOff;

        // S = (Q/8) @ K^T  (4 key-groups of 16 x 4 k-steps)
        float s[8][4];
        #pragma unroll
        for (int nt = 0; nt < 8; nt++)
            s[nt][0] = s[nt][1] = s[nt][2] = s[nt][3] = 0.f;
        #pragma unroll
        for (int ks = 0; ks < 4; ks++) {
            #pragma unroll
            for (int g = 0; g < 4; g++) {
                uint32_t t[4];
                ldm4(t, kFrag + (uint32_t)(g * 16 * SD + ks * 16) * 2);
                uint32_t b0[2] = { t[0], t[2] };
                uint32_t b1[2] = { t[1], t[3] };
                mma_f16(s[2 * g],     aq[ks], b0);
                mma_f16(s[2 * g + 1], aq[ks], b1);
            }
        }

        // Online softmax
        float tm0 = -1e30f, tm1 = -1e30f;
        #pragma unroll
        for (int nt = 0; nt < 8; nt++) {
            tm0 = fmaxf(tm0, fmaxf(s[nt][0], s[nt][1]));
            tm1 = fmaxf(tm1, fmaxf(s[nt][2], s[nt][3]));
        }
        #pragma unroll
        for (int o = 1; o <= 2; o <<= 1) {
            tm0 = fmaxf(tm0, __shfl_xor_sync(0xffffffffu, tm0, o));
            tm1 = fmaxf(tm1, __shfl_xor_sync(0xffffffffu, tm1, o));
        }
        float mn0 = fmaxf(m0, tm0), mn1 = fmaxf(m1, tm1);
        float c0 = __expf(m0 - mn0), c1 = __expf(m1 - mn1);
        l0 *= c0; l1 *= c1;
        #pragma unroll
        for (int nt = 0; nt < 8; nt++) {
            O[nt][0] *= c0; O[nt][1] *= c0;
            O[nt][2] *= c1; O[nt][3] *= c1;
        }
        float ls0 = 0.f, ls1 = 0.f;
        #pragma unroll
        for (int nt = 0; nt < 8; nt++) {
            s[nt][0] = __expf(s[nt][0] - mn0);
            s[nt][1] = __expf(s[nt][1] - mn0);
            s[nt][2] = __expf(s[nt][2] - mn1);
            s[nt][3] = __expf(s[nt][3] - mn1);
            ls0 += s[nt][0] + s[nt][1];
            ls1 += s[nt][2] + s[nt][3];
        }
        #pragma unroll
        for (int o = 1; o <= 2; o <<= 1) {
            ls0 += __shfl_xor_sync(0xffffffffu, ls0, o);
            ls1 += __shfl_xor_sync(0xffffffffu, ls1, o);
        }
        l0 += ls0; l1 += ls1;
        m0 = mn0; m1 = mn1;

        // O += P @ V : A from accum (layout match), B via ldmatrix.trans
        #pragma unroll
        for (int j = 0; j < 4; j++) {           // key-groups of 16
            uint32_t a[4];
            a[0] = pack_h2(s[2 * j][0],     s[2 * j][1]);
            a[1] = pack_h2(s[2 * j][2],     s[2 * j][3]);
            a[2] = pack_h2(s[2 * j + 1][0], s[2 * j + 1][1]);
            a[3] = pack_h2(s[2 * j + 1][2], s[2 * j + 1][3]);
            #pragma unroll
            for (int g = 0; g < 4; g++) {       // dim-groups of 16
                uint32_t t[4];
                ldm4t(t, vFrag + (uint32_t)(j * 16 * SD + g * 16) * 2);
                uint32_t b0[2] = { t[0], t[1] };
                uint32_t b1[2] = { t[2], t[3] };
                mma_f16(O[2 * g],     a, b0);
                mma_f16(O[2 * g + 1], a, b1);
            }
        }
    }

    float inv0 = 1.f / l0, inv1 = 1.f / l1;
    const int row0 = qbase + wid * 16 + lr;
    uint32_t* o0 = out + ((size_t)row0 * HDIM + head * 64) / 2;
    uint32_t* o1 = o0 + 4 * HDIM;
    #pragma unroll
    for (int nt = 0; nt < 8; nt++) {
        o0[(nt * 8 + lc * 2) / 2] = pack_h2(O[nt][0] * inv0, O[nt][1] * inv0);
        o1[(nt * 8 + lc * 2) / 2] = pack_h2(O[nt][2] * inv1, O[nt][3] * inv1);
    }
}

// ---------------------------------------------------------------------------
extern "C" void kernel_launch(void* const* d_in, const int* in_sizes, int n_in,
                              void* d_out, int out_size)
{
    const float* x        = (const float*)d_in[0];
    const float* wqkv     = (const float*)d_in[1];
    const float* wo       = (const float*)d_in[2];
    const float* ln0_g    = (const float*)d_in[3];
    const float* ln0_b    = (const float*)d_in[4];
    const float* ln1_g    = (const float*)d_in[5];
    const float* ln1_b    = (const float*)d_in[6];
    const float* fc0_w    = (const float*)d_in[7];
    const float* fc0_b    = (const float*)d_in[8];
    const float* fc1_w    = (const float*)d_in[9];
    const float* fc1_b    = (const float*)d_in[10];
    const float* rope_cos = (const float*)d_in[11];
    const float* rope_sin = (const float*)d_in[12];
    float* out = (float*)d_out;

    __half *h, *qkv, *attn, *h2, *mid, *wqkv_t, *wo_t, *fc0_t, *fc1_t;
    float *x1;
    cudaGetSymbolAddress((void**)&h,      g_h);
    cudaGetSymbolAddress((void**)&qkv,    g_qkv);
    cudaGetSymbolAddress((void**)&attn,   g_attn);
    cudaGetSymbolAddress((void**)&x1,     g_x1);
    cudaGetSymbolAddress((void**)&h2,     g_h2);
    cudaGetSymbolAddress((void**)&mid,    g_mid);
    cudaGetSymbolAddress((void**)&wqkv_t, g_wqkv_t);
    cudaGetSymbolAddress((void**)&wo_t,   g_wo_t);
    cudaGetSymbolAddress((void**)&fc0_t,  g_fc0_t);
    cudaGetSymbolAddress((void**)&fc1_t,  g_fc1_t);

    cudaFuncSetAttribute(fa_kernel, cudaFuncAttributeMaxDynamicSharedMemorySize, ATTN_SMEM);
    cudaFuncSetAttribute(tc_gemm<4,1>, cudaFuncAttributeMaxDynamicSharedMemorySize, GEMM_SMEM);
    cudaFuncSetAttribute(tc_gemm<1,0>, cudaFuncAttributeMaxDynamicSharedMemorySize, GEMM_SMEM);
    cudaFuncSetAttribute(tc_gemm<2,1>, cudaFuncAttributeMaxDynamicSharedMemorySize, GEMM_SMEM);
    cudaFuncSetAttribute(tc_gemm<3,0>, cudaFuncAttributeMaxDynamicSharedMemorySize, GEMM_SMEM);

    // 0. single-launch weight converts f32 -> half (flat index, exact blocks)
    cvt_all_kernel<<<CVT_BLOCKS, 256>>>(wqkv, wo, fc0_w, fc1_w,
                                        (uint32_t*)wqkv_t, (uint32_t*)wo_t,
                                        (uint32_t*)fc0_t, (uint32_t*)fc1_t);

    // 1. ln0 -> half
    ln_kernel<<<S_TOK / 8, 256>>>(x, ln0_g, ln0_b, (uint32_t*)h);
    // 2. qkv = h @ wqkv^T with fused rope -> half
    tc_gemm<4,1><<<dim3(3 * HDIM / 128, S_TOK / 128), 256, GEMM_SMEM>>>(
        h, wqkv_t, qkv, nullptr, nullptr, rope_cos, rope_sin, S_TOK, 3 * HDIM, HDIM);
    // 3. attention -> half
    fa_kernel<<<dim3(LSEG / 128, NHEAD, NSEG), 256, ATTN_SMEM>>>(qkv, (uint32_t*)attn);
    // 4. x1 = x + attn @ wo^T -> f32
    tc_gemm<1,0><<<dim3(HDIM / 128, S_TOK / 128), 256, GEMM_SMEM>>>(
        attn, wo_t, x1, nullptr, x, nullptr, nullptr, S_TOK, HDIM, HDIM);
    // 5. ln1 -> half
    ln_kernel<<<S_TOK / 8, 256>>>(x1, ln1_g, ln1_b, (uint32_t*)h2);
    // 6. mid = gelu(h2 @ fc0^T + b) -> half
    tc_gemm<2,1><<<dim3(MLPD / 128, S_TOK / 128), 256, GEMM_SMEM>>>(
        h2, fc0_t, mid, fc0_b, nullptr, nullptr, nullptr, S_TOK, MLPD, HDIM);
    // 7. out = x1 + mid @ fc1^T + b -> f32
    tc_gemm<3,0><<<dim3(HDIM / 128, S_TOK / 128), 256, GEMM_SMEM>>>(
        mid, fc1_t, out, fc1_b, x1, nullptr, nullptr, S_TOK, HDIM, MLPD);
}